// round 3
// baseline (speedup 1.0000x reference)
#include <cuda_runtime.h>

#define D_MODEL 256
#define D_CLIP 768
#define NHEAD 8
#define HEAD_DIM 32
#define Q_LEN 100
#define BATCH 32
#define T_LEN 1203
#define NROWS (Q_LEN * BATCH)   // 3200
#define NSPLIT 2
#define THALF 602               // split 0: [0,602), split 1: [602,1203)
#define LOG2E 1.4426950408889634f

typedef unsigned long long u64;

// ---- scratch (device globals; no allocation allowed) ----
__device__ float g_K[NHEAD * T_LEN * HEAD_DIM];   // normalized K * scale*(1-alpha_h)*log2e
__device__ float g_V[NHEAD * T_LEN * HEAD_DIM];
__device__ float g_Q[BATCH * NHEAD * Q_LEN * HEAD_DIM];            // normalized Q, [b][h][q][d]
__device__ float g_AO[NSPLIT * BATCH * NHEAD * Q_LEN * HEAD_DIM];  // unnormalized partial att out
__device__ float g_L[NSPLIT * BATCH * NHEAD * Q_LEN];              // partial exp-sums
// packed transposed weights: WT4[c4*256 + j] = float4 of W[j][4c4 .. 4c4+3]
__device__ float g_WqT4[D_MODEL * D_MODEL];
__device__ float g_WkT4[D_MODEL * D_CLIP];
__device__ float g_WvT4[D_MODEL * D_CLIP];
__device__ float g_WoT4[D_MODEL * D_MODEL];

// ---- packed fp32x2 helpers (Blackwell FFMA2) ----
__device__ __forceinline__ u64 pk2(float lo, float hi) {
    u64 r; asm("mov.b64 %0, {%1, %2};" : "=l"(r) : "f"(lo), "f"(hi)); return r;
}
__device__ __forceinline__ void unpk2(u64 v, float& lo, float& hi) {
    asm("mov.b64 {%0, %1}, %2;" : "=f"(lo), "=f"(hi) : "l"(v));
}
__device__ __forceinline__ u64 fma2(u64 a, u64 b, u64 c) {
    u64 d; asm("fma.rn.f32x2 %0, %1, %2, %3;" : "=l"(d) : "l"(a), "l"(b), "l"(c)); return d;
}
__device__ __forceinline__ u64 mul2(u64 a, u64 b) {
    u64 d; asm("mul.rn.f32x2 %0, %1, %2;" : "=l"(d) : "l"(a), "l"(b)); return d;
}
__device__ __forceinline__ u64 add2(u64 a, u64 b) {
    u64 d; asm("add.rn.f32x2 %0, %1, %2;" : "=l"(d) : "l"(a), "l"(b)); return d;
}
__device__ __forceinline__ float hsum2(u64 v) { float lo, hi; unpk2(v, lo, hi); return lo + hi; }
__device__ __forceinline__ float ex2(float x) {
    float r; asm("ex2.approx.f32 %0, %1;" : "=f"(r) : "f"(x)); return r;
}

// ============================================================================
// Kernel 0a: pack both 256x256 weights (Wq, Wo) in one launch
// ============================================================================
__global__ void pack2_kernel(const float* __restrict__ A, float* __restrict__ AT,
                             const float* __restrict__ B, float* __restrict__ BT)
{
    const int n4 = D_MODEL >> 2;          // 64
    const int per = D_MODEL * n4;         // 16384
    for (int idx = blockIdx.x * blockDim.x + threadIdx.x; idx < 2 * per; idx += gridDim.x * blockDim.x) {
        int m = idx >= per;
        int id = idx - m * per;
        int j = id / n4, c4 = id - j * n4;
        const float* src = m ? B : A;
        float* dst = m ? BT : AT;
        float4 v = ((const float4*)(src + (size_t)j * D_MODEL))[c4];
        ((float4*)dst)[(size_t)c4 * D_MODEL + j] = v;
    }
}

// Kernel 0b: generic pack W[256][IN] -> WT4[c4*256 + j]
__global__ void pack_kernel(const float* __restrict__ W, float* __restrict__ WT4, int IN)
{
    const int n4 = IN >> 2;
    const int total = D_MODEL * n4;
    for (int idx = blockIdx.x * blockDim.x + threadIdx.x; idx < total; idx += gridDim.x * blockDim.x) {
        int j = idx / n4, c4 = idx - j * n4;
        float4 v = ((const float4*)(W + (size_t)j * IN))[c4];
        ((float4*)WT4)[(size_t)c4 * D_MODEL + j] = v;
    }
}

// ============================================================================
// Kernel 1: K/V projection + per-head l2norm of K, folding scale*(1-a_h)*log2e
// ============================================================================
#define ROWS_KV 8
__global__ __launch_bounds__(256, 2) void kv_kernel(
    const float* __restrict__ text, const float* __restrict__ bk,
    const float* __restrict__ bv, const float* __restrict__ lsp)
{
    __shared__ float s_text[ROWS_KV][D_CLIP];   // 24 KB
    const int tid = threadIdx.x;
    const int t0 = blockIdx.x * ROWS_KV;
    const int nrows = min(ROWS_KV, T_LEN - t0);

    for (int idx = tid; idx < ROWS_KV * (D_CLIP / 4); idx += 256) {
        int r = idx / (D_CLIP / 4);
        int c4 = idx % (D_CLIP / 4);
        float4 v = make_float4(0.f, 0.f, 0.f, 0.f);
        if (r < nrows) v = ((const float4*)(text + (size_t)(t0 + r) * D_CLIP))[c4];
        ((float4*)(&s_text[r][0]))[c4] = v;
    }
    __syncthreads();

    const int j = tid, head = j >> 5, lane = j & 31;
    u64 akA[ROWS_KV], akB[ROWS_KV], avA[ROWS_KV], avB[ROWS_KV];
#pragma unroll
    for (int r = 0; r < ROWS_KV; ++r) { akA[r] = akB[r] = avA[r] = avB[r] = 0ull; }

    const ulonglong2* wkp = ((const ulonglong2*)g_WkT4) + j;
    const ulonglong2* wvp = ((const ulonglong2*)g_WvT4) + j;
#pragma unroll 2
    for (int c4 = 0; c4 < D_CLIP / 4; ++c4) {
        ulonglong2 wk4 = wkp[(size_t)c4 * D_MODEL];
        ulonglong2 wv4 = wvp[(size_t)c4 * D_MODEL];
#pragma unroll
        for (int r = 0; r < ROWS_KV; ++r) {
            ulonglong2 x = *(const ulonglong2*)(&s_text[r][4 * c4]);
            akA[r] = fma2(x.x, wk4.x, akA[r]);
            akB[r] = fma2(x.y, wk4.y, akB[r]);
            avA[r] = fma2(x.x, wv4.x, avA[r]);
            avB[r] = fma2(x.y, wv4.y, avB[r]);
        }
    }

    const float scale = fminf(expf(lsp[0]), 100.0f);
    const float kfac = scale * (1.0f - (float)head * (1.0f / 7.0f)) * LOG2E;
    const float bkj = bk[j], bvj = bv[j];
    for (int r = 0; r < nrows; ++r) {
        float kk = hsum2(akA[r]) + hsum2(akB[r]) + bkj;
        float ss = kk * kk;
#pragma unroll
        for (int off = 16; off > 0; off >>= 1) ss += __shfl_xor_sync(0xffffffffu, ss, off);
        float val = kk / fmaxf(sqrtf(ss), 1e-6f) * kfac;
        int t = t0 + r;
        g_K[(head * T_LEN + t) * HEAD_DIM + lane] = val;
        g_V[(head * T_LEN + t) * HEAD_DIM + lane] = hsum2(avA[r]) + hsum2(avB[r]) + bvj;
    }
}

// ============================================================================
// Kernel 2: Q projection + per-head l2norm, written as [b][h][q][d]
// ============================================================================
#define ROWS_Q 16
__global__ __launch_bounds__(256, 2) void q_kernel(
    const float* __restrict__ tgt, const float* __restrict__ qpos,
    const float* __restrict__ bq)
{
    __shared__ float s_in[ROWS_Q][D_MODEL];   // 16 KB
    const int tid = threadIdx.x;
    const int r0 = blockIdx.x * ROWS_Q;

    for (int idx = tid; idx < ROWS_Q * (D_MODEL / 4); idx += 256) {
        int r = idx >> 6, c4 = idx & 63;
        const float4 a = ((const float4*)(tgt  + (size_t)(r0 + r) * D_MODEL))[c4];
        const float4 p = ((const float4*)(qpos + (size_t)(r0 + r) * D_MODEL))[c4];
        ((float4*)(&s_in[r][0]))[c4] = make_float4(a.x + p.x, a.y + p.y, a.z + p.z, a.w + p.w);
    }
    __syncthreads();

    const int j = tid, head = j >> 5, lane = j & 31;
    u64 aA[ROWS_Q], aB[ROWS_Q];
#pragma unroll
    for (int r = 0; r < ROWS_Q; ++r) { aA[r] = aB[r] = 0ull; }

    const ulonglong2* wqp = ((const ulonglong2*)g_WqT4) + j;
#pragma unroll 2
    for (int c4 = 0; c4 < D_MODEL / 4; ++c4) {
        ulonglong2 w4 = wqp[(size_t)c4 * D_MODEL];
#pragma unroll
        for (int r = 0; r < ROWS_Q; ++r) {
            ulonglong2 x = *(const ulonglong2*)(&s_in[r][4 * c4]);
            aA[r] = fma2(x.x, w4.x, aA[r]);
            aB[r] = fma2(x.y, w4.y, aB[r]);
        }
    }

    const float bqj = bq[j];
    for (int r = 0; r < ROWS_Q; ++r) {
        float qq = hsum2(aA[r]) + hsum2(aB[r]) + bqj;
        float ss = qq * qq;
#pragma unroll
        for (int off = 16; off > 0; off >>= 1) ss += __shfl_xor_sync(0xffffffffu, ss, off);
        float val = qq / fmaxf(sqrtf(ss), 1e-6f);
        int row = r0 + r;
        int qi = row >> 5, b = row & 31;                 // row = qi*32 + b
        g_Q[(((b * NHEAD) + head) * Q_LEN + qi) * HEAD_DIM + lane] = val;
    }
}

// ============================================================================
// Kernel 3: attention, batch-paired + split-K over T.
// grid (h, b-pair, split); 128 threads; thread tid<100 handles query tid for
// BOTH batches of the pair (K/V LDS shared). exp via ex2 (log2e pre-folded).
// Stores UNNORMALIZED output + exp-sum; proj combines the splits.
// ============================================================================
#define TT 64
// s_u: union of q-stage (2*100*32 floats) and oov tile (2*100*(TT+1) floats)
#define SU_FLOATS (2 * Q_LEN * (TT + 1))
__global__ __launch_bounds__(128, 2) void attn_kernel(const float* __restrict__ oov)
{
    const int h = blockIdx.x, bp = blockIdx.y, s = blockIdx.z;
    const int b0 = 2 * bp, b1 = 2 * bp + 1;
    const int t_begin = s * THALF;
    const int t_end = (s == 0) ? THALF : T_LEN;
    extern __shared__ float sm[];
    float* s_k = sm;                          // TT*32
    float* s_v = s_k + TT * HEAD_DIM;         // TT*32
    float* s_u = s_v + TT * HEAD_DIM;         // SU_FLOATS
    const int tid = threadIdx.x;

    // stage Q rows for both batches: s_u[0..3200) = b0, [3200..6400) = b1
    {
        const float4* gq0 = (const float4*)(g_Q + (size_t)(b0 * NHEAD + h) * Q_LEN * HEAD_DIM);
        const float4* gq1 = (const float4*)(g_Q + (size_t)(b1 * NHEAD + h) * Q_LEN * HEAD_DIM);
        for (int idx = tid; idx < Q_LEN * HEAD_DIM / 4; idx += 128) {
            ((float4*)s_u)[idx] = gq0[idx];
            ((float4*)s_u)[Q_LEN * HEAD_DIM / 4 + idx] = gq1[idx];
        }
    }
    __syncthreads();

    const bool active = tid < Q_LEN;
    u64 qa[HEAD_DIM / 2], qb[HEAD_DIM / 2];
    if (active) {
        const u64* p0 = (const u64*)(s_u + tid * HEAD_DIM);
        const u64* p1 = (const u64*)(s_u + (Q_LEN + tid) * HEAD_DIM);
#pragma unroll
        for (int jj = 0; jj < 16; ++jj) { qa[jj] = p0[jj]; qb[jj] = p1[jj]; }
    }
    u64 aoa[HEAD_DIM / 2], aob[HEAD_DIM / 2];
#pragma unroll
    for (int jj = 0; jj < 16; ++jj) { aoa[jj] = 0ull; aob[jj] = 0ull; }
    float la = 0.f, lb = 0.f;

    const float ap = (float)h * (1.0f / 7.0f) * LOG2E;   // alpha * log2e
    const bool use_qk = (h != NHEAD - 1);
    const bool use_ov = (h != 0);
    const float* o0 = oov + (size_t)b0 * Q_LEN * T_LEN;
    const float* o1 = oov + (size_t)b1 * Q_LEN * T_LEN;

    const int tt_tid = tid & 63;       // t-index for oov staging
    const int su_half = tid >> 6;      // 0 -> b0 rows, 1 -> b1 rows

    for (int t0 = t_begin; t0 < t_end; t0 += TT) {
        const int tt = min(TT, t_end - t0);
        __syncthreads();
        {
            const float4* gk = (const float4*)(g_K + (size_t)(h * T_LEN + t0) * HEAD_DIM);
            const float4* gv = (const float4*)(g_V + (size_t)(h * T_LEN + t0) * HEAD_DIM);
            for (int idx = tid; idx < tt * (HEAD_DIM / 4); idx += 128) {
                ((float4*)s_k)[idx] = gk[idx];
                ((float4*)s_v)[idx] = gv[idx];
            }
            if (use_ov && tt_tid < tt) {
                const float* src = (su_half ? o1 : o0) + t0 + tt_tid;
                float* dst = s_u + (su_half * Q_LEN) * (TT + 1) + tt_tid;
#pragma unroll 4
                for (int r = 0; r < Q_LEN; ++r)
                    dst[r * (TT + 1)] = ap * src[(size_t)r * T_LEN];
            }
        }
        __syncthreads();
        if (active) {
            const float* soa = s_u + tid * (TT + 1);
            const float* sob = s_u + (Q_LEN + tid) * (TT + 1);
            for (int t = 0; t < tt; ++t) {
                float lg0 = 0.f, lg1 = 0.f;
                if (use_qk) {
                    const ulonglong2* kp = (const ulonglong2*)(s_k + t * HEAD_DIM);
                    ulonglong2 k0 = kp[0], k1 = kp[1], k2 = kp[2], k3 = kp[3];
                    u64 a0 = mul2(qa[0], k0.x), b0_ = mul2(qb[0], k0.x);
                    u64 a1 = mul2(qa[1], k0.y), b1_ = mul2(qb[1], k0.y);
                    u64 a2 = mul2(qa[2], k1.x), b2_ = mul2(qb[2], k1.x);
                    u64 a3 = mul2(qa[3], k1.y), b3_ = mul2(qb[3], k1.y);
                    a0 = fma2(qa[4], k2.x, a0); b0_ = fma2(qb[4], k2.x, b0_);
                    a1 = fma2(qa[5], k2.y, a1); b1_ = fma2(qb[5], k2.y, b1_);
                    a2 = fma2(qa[6], k3.x, a2); b2_ = fma2(qb[6], k3.x, b2_);
                    a3 = fma2(qa[7], k3.y, a3); b3_ = fma2(qb[7], k3.y, b3_);
                    ulonglong2 k4 = kp[4], k5 = kp[5], k6 = kp[6], k7 = kp[7];
                    a0 = fma2(qa[8], k4.x, a0);  b0_ = fma2(qb[8], k4.x, b0_);
                    a1 = fma2(qa[9], k4.y, a1);  b1_ = fma2(qb[9], k4.y, b1_);
                    a2 = fma2(qa[10], k5.x, a2); b2_ = fma2(qb[10], k5.x, b2_);
                    a3 = fma2(qa[11], k5.y, a3); b3_ = fma2(qb[11], k5.y, b3_);
                    a0 = fma2(qa[12], k6.x, a0); b0_ = fma2(qb[12], k6.x, b0_);
                    a1 = fma2(qa[13], k6.y, a1); b1_ = fma2(qb[13], k6.y, b1_);
                    a2 = fma2(qa[14], k7.x, a2); b2_ = fma2(qb[14], k7.x, b2_);
                    a3 = fma2(qa[15], k7.y, a3); b3_ = fma2(qb[15], k7.y, b3_);
                    a0 = add2(a0, a1); a2 = add2(a2, a3); a0 = add2(a0, a2);
                    b0_ = add2(b0_, b1_); b2_ = add2(b2_, b3_); b0_ = add2(b0_, b2_);
                    lg0 = hsum2(a0);
                    lg1 = hsum2(b0_);
                }
                if (use_ov) { lg0 += soa[t]; lg1 += sob[t]; }
                const float p0 = ex2(lg0), p1 = ex2(lg1);
                la += p0; lb += p1;
                const u64 pp0 = pk2(p0, p0), pp1 = pk2(p1, p1);
                const ulonglong2* vp = (const ulonglong2*)(s_v + t * HEAD_DIM);
#pragma unroll
                for (int jj = 0; jj < 8; ++jj) {
                    ulonglong2 vv = vp[jj];
                    aoa[2 * jj]     = fma2(pp0, vv.x, aoa[2 * jj]);
                    aoa[2 * jj + 1] = fma2(pp0, vv.y, aoa[2 * jj + 1]);
                    aob[2 * jj]     = fma2(pp1, vv.x, aob[2 * jj]);
                    aob[2 * jj + 1] = fma2(pp1, vv.y, aob[2 * jj + 1]);
                }
            }
        }
    }

    if (active) {
        const size_t base0 = ((size_t)((s * BATCH + b0) * NHEAD + h) * Q_LEN + tid);
        const size_t base1 = ((size_t)((s * BATCH + b1) * NHEAD + h) * Q_LEN + tid);
        g_L[base0] = la;
        g_L[base1] = lb;
        float* d0 = g_AO + base0 * HEAD_DIM;
        float* d1 = g_AO + base1 * HEAD_DIM;
#pragma unroll
        for (int jj = 0; jj < 16; ++jj) {
            float lo, hi;
            unpk2(aoa[jj], lo, hi); d0[2 * jj] = lo; d0[2 * jj + 1] = hi;
            unpk2(aob[jj], lo, hi); d1[2 * jj] = lo; d1[2 * jj + 1] = hi;
        }
    }
}

// ============================================================================
// Kernel 4: combine attention splits + output projection + residual + LayerNorm
// ============================================================================
#define ROWS_P 16
__global__ __launch_bounds__(256, 2) void proj_kernel(
    const float* __restrict__ tgt, const float* __restrict__ bo,
    const float* __restrict__ ln_g, const float* __restrict__ ln_b, float* __restrict__ out)
{
    __shared__ float s_att[ROWS_P][D_MODEL];
    __shared__ float s_y[ROWS_P][D_MODEL];
    __shared__ float s_mu[ROWS_P], s_rs[ROWS_P];
    const int tid = threadIdx.x;
    const int r0 = blockIdx.x * ROWS_P;
    const int j = tid, head = j >> 5, lane = j & 31;

    for (int r = 0; r < ROWS_P; ++r) {
        int row = r0 + r, qi = row >> 5, b = row & 31;
        size_t base0 = (size_t)((b * NHEAD) + head) * Q_LEN + qi;
        size_t base1 = (size_t)(BATCH * NHEAD * Q_LEN) + base0;
        float inv = 1.0f / (g_L[base0] + g_L[base1]);
        float a0 = g_AO[base0 * HEAD_DIM + lane];
        float a1 = g_AO[base1 * HEAD_DIM + lane];
        s_att[r][j] = (a0 + a1) * inv;
    }
    __syncthreads();

    u64 accA[ROWS_P], accB[ROWS_P];
#pragma unroll
    for (int r = 0; r < ROWS_P; ++r) { accA[r] = accB[r] = 0ull; }
    const ulonglong2* wop = ((const ulonglong2*)g_WoT4) + j;
#pragma unroll 2
    for (int c4 = 0; c4 < D_MODEL / 4; ++c4) {
        ulonglong2 w4 = wop[(size_t)c4 * D_MODEL];
#pragma unroll
        for (int r = 0; r < ROWS_P; ++r) {
            ulonglong2 x = *(const ulonglong2*)(&s_att[r][4 * c4]);
            accA[r] = fma2(x.x, w4.x, accA[r]);
            accB[r] = fma2(x.y, w4.y, accB[r]);
        }
    }

    const float boj = bo[j];
    for (int r = 0; r < ROWS_P; ++r) {
        int row = r0 + r;
        s_y[r][j] = hsum2(accA[r]) + hsum2(accB[r]) + boj + tgt[(size_t)row * D_MODEL + j];
    }
    __syncthreads();

    {
        const int w = tid >> 5, ln = tid & 31;
#pragma unroll
        for (int rr = 0; rr < 2; ++rr) {
            int r = 2 * w + rr;
            float s = 0.f, sq = 0.f;
            for (int c = ln; c < D_MODEL; c += 32) { float v = s_y[r][c]; s += v; sq += v * v; }
#pragma unroll
            for (int off = 16; off > 0; off >>= 1) {
                s  += __shfl_xor_sync(0xffffffffu, s, off);
                sq += __shfl_xor_sync(0xffffffffu, sq, off);
            }
            if (ln == 0) {
                float mu = s * (1.0f / D_MODEL);
                s_mu[r] = mu;
                s_rs[r] = rsqrtf(sq * (1.0f / D_MODEL) - mu * mu + 1e-5f);
            }
        }
    }
    __syncthreads();

    const float g = ln_g[j], bb = ln_b[j];
    for (int r = 0; r < ROWS_P; ++r) {
        int row = r0 + r;
        out[(size_t)row * D_MODEL + j] = (s_y[r][j] - s_mu[r]) * s_rs[r] * g + bb;
    }
}

// ============================================================================
extern "C" void kernel_launch(void* const* d_in, const int* in_sizes, int n_in,
                              void* d_out, int out_size)
{
    const float* tgt  = (const float*)d_in[0];
    const float* text = (const float*)d_in[1];
    const float* qpos = (const float*)d_in[2];
    const float* oov  = (const float*)d_in[3];
    const float* Wq   = (const float*)d_in[4];
    const float* bq   = (const float*)d_in[5];
    const float* Wk   = (const float*)d_in[6];
    const float* bk   = (const float*)d_in[7];
    const float* Wv   = (const float*)d_in[8];
    const float* bv   = (const float*)d_in[9];
    const float* Wo   = (const float*)d_in[10];
    const float* bo   = (const float*)d_in[11];
    const float* lng  = (const float*)d_in[12];
    const float* lnb  = (const float*)d_in[13];
    const float* ls   = (const float*)d_in[14];
    float* out = (float*)d_out;

    float *wqT4, *wkT4, *wvT4, *woT4;
    cudaGetSymbolAddress((void**)&wqT4, g_WqT4);
    cudaGetSymbolAddress((void**)&wkT4, g_WkT4);
    cudaGetSymbolAddress((void**)&wvT4, g_WvT4);
    cudaGetSymbolAddress((void**)&woT4, g_WoT4);

    // exactly 5 launches before attn so ncu (-s 5 -c 1) captures attn_kernel
    pack2_kernel<<<128, 256>>>(Wq, wqT4, Wo, woT4);     // 1
    pack_kernel<<<256, 256>>>(Wk, wkT4, D_CLIP);        // 2
    pack_kernel<<<256, 256>>>(Wv, wvT4, D_CLIP);        // 3
    kv_kernel<<<(T_LEN + ROWS_KV - 1) / ROWS_KV, 256>>>(text, bk, bv, ls);   // 4
    q_kernel<<<NROWS / ROWS_Q, 256>>>(tgt, qpos, bq);   // 5

    const int att_smem = (2 * TT * HEAD_DIM + SU_FLOATS) * (int)sizeof(float);
    cudaFuncSetAttribute(attn_kernel, cudaFuncAttributeMaxDynamicSharedMemorySize, att_smem);
    attn_kernel<<<dim3(NHEAD, BATCH / 2, NSPLIT), 128, att_smem>>>(oov);     // 6 <- profiled

    proj_kernel<<<NROWS / ROWS_P, 256>>>(tgt, bo, lng, lnb, out);            // 7
}

// round 5
// speedup vs baseline: 1.5505x; 1.5505x over previous
#include <cuda_runtime.h>

#define D_MODEL 256
#define D_CLIP 768
#define NHEAD 8
#define HEAD_DIM 32
#define Q_LEN 100
#define BATCH 32
#define T_LEN 1203
#define NROWS (Q_LEN * BATCH)   // 3200
#define NSPLIT 2
#define THALF 602               // split 0: [0,602), split 1: [602,1203)
#define LOG2E 1.4426950408889634f

typedef unsigned long long u64;

// ---- scratch (device globals; no allocation allowed) ----
__device__ float g_K[NHEAD * T_LEN * HEAD_DIM];   // normalized K * scale*(1-alpha_h)*log2e
__device__ float g_V[NHEAD * T_LEN * HEAD_DIM];
__device__ float g_Q[BATCH * NHEAD * Q_LEN * HEAD_DIM];            // normalized Q, [b][h][q][d]
__device__ float g_AO[NSPLIT * BATCH * NHEAD * Q_LEN * HEAD_DIM];  // unnormalized partial att out
__device__ float g_L[NSPLIT * BATCH * NHEAD * Q_LEN];              // partial exp-sums
// packed transposed weights: WT4[c4*256 + j] = float4 of W[j][4c4 .. 4c4+3]
__device__ float g_WqT4[D_MODEL * D_MODEL];
__device__ float g_WkT4[D_MODEL * D_CLIP];
__device__ float g_WvT4[D_MODEL * D_CLIP];
__device__ float g_WoT4[D_MODEL * D_MODEL];

// ---- packed fp32x2 helpers (Blackwell FFMA2) ----
__device__ __forceinline__ u64 pk2(float lo, float hi) {
    u64 r; asm("mov.b64 %0, {%1, %2};" : "=l"(r) : "f"(lo), "f"(hi)); return r;
}
__device__ __forceinline__ void unpk2(u64 v, float& lo, float& hi) {
    asm("mov.b64 {%0, %1}, %2;" : "=f"(lo), "=f"(hi) : "l"(v));
}
__device__ __forceinline__ u64 fma2(u64 a, u64 b, u64 c) {
    u64 d; asm("fma.rn.f32x2 %0, %1, %2, %3;" : "=l"(d) : "l"(a), "l"(b), "l"(c)); return d;
}
__device__ __forceinline__ u64 mul2(u64 a, u64 b) {
    u64 d; asm("mul.rn.f32x2 %0, %1, %2;" : "=l"(d) : "l"(a), "l"(b)); return d;
}
__device__ __forceinline__ u64 add2(u64 a, u64 b) {
    u64 d; asm("add.rn.f32x2 %0, %1, %2;" : "=l"(d) : "l"(a), "l"(b)); return d;
}
__device__ __forceinline__ float hsum2(u64 v) { float lo, hi; unpk2(v, lo, hi); return lo + hi; }
__device__ __forceinline__ float ex2(float x) {
    float r; asm("ex2.approx.f32 %0, %1;" : "=f"(r) : "f"(x)); return r;
}

// ============================================================================
// Kernel 0: pack ALL weights in one launch.
// Segments (in float4 units): Wq 16384 | Wk 49152 | Wv 49152 | Wo 16384.
// ============================================================================
__global__ void pack_all_kernel(const float* __restrict__ Wq, const float* __restrict__ Wk,
                                const float* __restrict__ Wv, const float* __restrict__ Wo)
{
    const int idx = blockIdx.x * blockDim.x + threadIdx.x;   // grid covers 131072 exactly
    const float* src; float* dst; int n4, id;
    if (idx < 16384)       { src = Wq; dst = g_WqT4; n4 = 64;  id = idx; }
    else if (idx < 65536)  { src = Wk; dst = g_WkT4; n4 = 192; id = idx - 16384; }
    else if (idx < 114688) { src = Wv; dst = g_WvT4; n4 = 192; id = idx - 65536; }
    else                   { src = Wo; dst = g_WoT4; n4 = 64;  id = idx - 114688; }
    int j = id / n4, c4 = id - j * n4;
    float4 v = ((const float4*)src)[(size_t)j * n4 + c4];
    ((float4*)dst)[(size_t)c4 * D_MODEL + j] = v;
}

// ============================================================================
// Kernel 1: K or V projection (blockIdx.y selects matrix). K branch adds
// per-head l2norm and folds scale*(1-alpha_h)*log2e.
// ============================================================================
#define ROWS_KV 8
__global__ __launch_bounds__(256, 3) void kv_kernel(
    const float* __restrict__ text, const float* __restrict__ bk,
    const float* __restrict__ bv, const float* __restrict__ lsp)
{
    __shared__ float s_text[ROWS_KV][D_CLIP];   // 24 KB
    const int tid = threadIdx.x;
    const int t0 = blockIdx.x * ROWS_KV;
    const int isV = blockIdx.y;
    const int nrows = min(ROWS_KV, T_LEN - t0);

    for (int idx = tid; idx < ROWS_KV * (D_CLIP / 4); idx += 256) {
        int r = idx / (D_CLIP / 4);
        int c4 = idx % (D_CLIP / 4);
        float4 v = make_float4(0.f, 0.f, 0.f, 0.f);
        if (r < nrows) v = ((const float4*)(text + (size_t)(t0 + r) * D_CLIP))[c4];
        ((float4*)(&s_text[r][0]))[c4] = v;
    }
    __syncthreads();

    const int j = tid, head = j >> 5, lane = j & 31;
    u64 aA[ROWS_KV], aB[ROWS_KV];
#pragma unroll
    for (int r = 0; r < ROWS_KV; ++r) { aA[r] = aB[r] = 0ull; }

    const ulonglong2* wp = ((const ulonglong2*)(isV ? g_WvT4 : g_WkT4)) + j;
#pragma unroll 4
    for (int c4 = 0; c4 < D_CLIP / 4; ++c4) {
        ulonglong2 w4 = wp[(size_t)c4 * D_MODEL];
#pragma unroll
        for (int r = 0; r < ROWS_KV; ++r) {
            ulonglong2 x = *(const ulonglong2*)(&s_text[r][4 * c4]);
            aA[r] = fma2(x.x, w4.x, aA[r]);
            aB[r] = fma2(x.y, w4.y, aB[r]);
        }
    }

    if (isV) {
        const float bvj = bv[j];
        for (int r = 0; r < nrows; ++r) {
            int t = t0 + r;
            g_V[(head * T_LEN + t) * HEAD_DIM + lane] = hsum2(aA[r]) + hsum2(aB[r]) + bvj;
        }
    } else {
        const float scale = fminf(expf(lsp[0]), 100.0f);
        const float kfac = scale * (1.0f - (float)head * (1.0f / 7.0f)) * LOG2E;
        const float bkj = bk[j];
        for (int r = 0; r < nrows; ++r) {
            float kk = hsum2(aA[r]) + hsum2(aB[r]) + bkj;
            float ss = kk * kk;
#pragma unroll
            for (int off = 16; off > 0; off >>= 1) ss += __shfl_xor_sync(0xffffffffu, ss, off);
            float val = kk / fmaxf(sqrtf(ss), 1e-6f) * kfac;
            int t = t0 + r;
            g_K[(head * T_LEN + t) * HEAD_DIM + lane] = val;
        }
    }
}

// ============================================================================
// Kernel 2: Q projection + per-head l2norm, written as [b][h][q][d]
// ============================================================================
#define ROWS_Q 8
__global__ __launch_bounds__(256, 4) void q_kernel(
    const float* __restrict__ tgt, const float* __restrict__ qpos,
    const float* __restrict__ bq)
{
    __shared__ float s_in[ROWS_Q][D_MODEL];   // 8 KB
    const int tid = threadIdx.x;
    const int r0 = blockIdx.x * ROWS_Q;

    for (int idx = tid; idx < ROWS_Q * (D_MODEL / 4); idx += 256) {
        int r = idx >> 6, c4 = idx & 63;
        const float4 a = ((const float4*)(tgt  + (size_t)(r0 + r) * D_MODEL))[c4];
        const float4 p = ((const float4*)(qpos + (size_t)(r0 + r) * D_MODEL))[c4];
        ((float4*)(&s_in[r][0]))[c4] = make_float4(a.x + p.x, a.y + p.y, a.z + p.z, a.w + p.w);
    }
    __syncthreads();

    const int j = tid, head = j >> 5, lane = j & 31;
    u64 aA[ROWS_Q], aB[ROWS_Q];
#pragma unroll
    for (int r = 0; r < ROWS_Q; ++r) { aA[r] = aB[r] = 0ull; }

    const ulonglong2* wqp = ((const ulonglong2*)g_WqT4) + j;
#pragma unroll 4
    for (int c4 = 0; c4 < D_MODEL / 4; ++c4) {
        ulonglong2 w4 = wqp[(size_t)c4 * D_MODEL];
#pragma unroll
        for (int r = 0; r < ROWS_Q; ++r) {
            ulonglong2 x = *(const ulonglong2*)(&s_in[r][4 * c4]);
            aA[r] = fma2(x.x, w4.x, aA[r]);
            aB[r] = fma2(x.y, w4.y, aB[r]);
        }
    }

    const float bqj = bq[j];
    for (int r = 0; r < ROWS_Q; ++r) {
        float qq = hsum2(aA[r]) + hsum2(aB[r]) + bqj;
        float ss = qq * qq;
#pragma unroll
        for (int off = 16; off > 0; off >>= 1) ss += __shfl_xor_sync(0xffffffffu, ss, off);
        float val = qq / fmaxf(sqrtf(ss), 1e-6f);
        int row = r0 + r;
        int qi = row >> 5, b = row & 31;                 // row = qi*32 + b
        g_Q[(((b * NHEAD) + head) * Q_LEN + qi) * HEAD_DIM + lane] = val;
    }
}

// ============================================================================
// Kernel 3: attention, split-K over T (round-2 structure). grid (h, b, split);
// 128 threads; thread = query row. ex2 softmax (log2e pre-folded into K and
// into staged alpha*oov). Stores UNNORMALIZED output + exp-sum.
// ============================================================================
#define TT 64
__global__ __launch_bounds__(128, 4) void attn_kernel(const float* __restrict__ oov)
{
    const int h = blockIdx.x, b = blockIdx.y, s = blockIdx.z;
    const int t_begin = s * THALF;
    const int t_end = (s == 0) ? THALF : T_LEN;
    extern __shared__ float sm[];
    float* s_q = sm;                                     // 3200
    float* s_k = sm + Q_LEN * HEAD_DIM;                  // TT*32
    float* s_v = s_k + TT * HEAD_DIM;                    // TT*32
    float* s_o = s_v + TT * HEAD_DIM;                    // 100*(TT+1)
    const int tid = threadIdx.x;

    {
        const float4* gq = (const float4*)(g_Q + (size_t)(b * NHEAD + h) * Q_LEN * HEAD_DIM);
        for (int idx = tid; idx < Q_LEN * HEAD_DIM / 4; idx += 128)
            ((float4*)s_q)[idx] = gq[idx];
    }
    __syncthreads();

    const bool active = tid < Q_LEN;
    u64 q2[HEAD_DIM / 2];
    if (active) {
        const u64* qp = (const u64*)(s_q + tid * HEAD_DIM);
#pragma unroll
        for (int jj = 0; jj < 16; ++jj) q2[jj] = qp[jj];
    }
    u64 ao[HEAD_DIM / 2];
#pragma unroll
    for (int jj = 0; jj < 16; ++jj) ao[jj] = 0ull;
    float l = 0.f;

    const float ap = (float)h * (1.0f / 7.0f) * LOG2E;   // alpha * log2e
    const bool use_qk = (h != NHEAD - 1);
    const bool use_ov = (h != 0);
    const float* oov_b = oov + (size_t)b * Q_LEN * T_LEN;

    for (int t0 = t_begin; t0 < t_end; t0 += TT) {
        const int tt = min(TT, t_end - t0);
        __syncthreads();
        {
            const float4* gk = (const float4*)(g_K + (size_t)(h * T_LEN + t0) * HEAD_DIM);
            const float4* gv = (const float4*)(g_V + (size_t)(h * T_LEN + t0) * HEAD_DIM);
            for (int idx = tid; idx < tt * (HEAD_DIM / 4); idx += 128) {
                ((float4*)s_k)[idx] = gk[idx];
                ((float4*)s_v)[idx] = gv[idx];
            }
            if (use_ov && tid < tt) {
                const float* src = oov_b + t0 + tid;
#pragma unroll 4
                for (int r = 0; r < Q_LEN; ++r)
                    s_o[r * (TT + 1) + tid] = ap * src[(size_t)r * T_LEN];
            }
        }
        __syncthreads();
        if (active) {
            const float* so = s_o + tid * (TT + 1);
#pragma unroll 2
            for (int t = 0; t < tt; ++t) {
                float lg = 0.f;
                if (use_qk) {
                    const ulonglong2* kp = (const ulonglong2*)(s_k + t * HEAD_DIM);
                    ulonglong2 k0 = kp[0], k1 = kp[1];
                    u64 a0 = mul2(q2[0], k0.x);
                    u64 a1 = mul2(q2[1], k0.y);
                    u64 a2 = mul2(q2[2], k1.x);
                    u64 a3 = mul2(q2[3], k1.y);
#pragma unroll
                    for (int jj = 1; jj < 4; ++jj) {
                        ulonglong2 ka = kp[2 * jj], kb = kp[2 * jj + 1];
                        a0 = fma2(q2[4 * jj + 0], ka.x, a0);
                        a1 = fma2(q2[4 * jj + 1], ka.y, a1);
                        a2 = fma2(q2[4 * jj + 2], kb.x, a2);
                        a3 = fma2(q2[4 * jj + 3], kb.y, a3);
                    }
                    a0 = add2(a0, a1); a2 = add2(a2, a3); a0 = add2(a0, a2);
                    lg = hsum2(a0);
                }
                if (use_ov) lg += so[t];
                const float p = ex2(lg);
                l += p;
                const u64 p2 = pk2(p, p);
                const ulonglong2* vp = (const ulonglong2*)(s_v + t * HEAD_DIM);
#pragma unroll
                for (int jj = 0; jj < 8; ++jj) {
                    ulonglong2 vv = vp[jj];
                    ao[2 * jj]     = fma2(p2, vv.x, ao[2 * jj]);
                    ao[2 * jj + 1] = fma2(p2, vv.y, ao[2 * jj + 1]);
                }
            }
        }
    }

    if (active) {
        const size_t base = ((size_t)((s * BATCH + b) * NHEAD + h) * Q_LEN + tid);
        g_L[base] = l;
        float* dst = g_AO + base * HEAD_DIM;
#pragma unroll
        for (int jj = 0; jj < 16; ++jj) {
            float lo, hi; unpk2(ao[jj], lo, hi);
            dst[2 * jj]     = lo;
            dst[2 * jj + 1] = hi;
        }
    }
}

// ============================================================================
// Kernel 4: combine attention splits + output projection + residual + LayerNorm
// ============================================================================
#define ROWS_P 8
__global__ __launch_bounds__(256, 4) void proj_kernel(
    const float* __restrict__ tgt, const float* __restrict__ bo,
    const float* __restrict__ ln_g, const float* __restrict__ ln_b, float* __restrict__ out)
{
    __shared__ float s_att[ROWS_P][D_MODEL];
    __shared__ float s_y[ROWS_P][D_MODEL];
    __shared__ float s_mu[ROWS_P], s_rs[ROWS_P];
    const int tid = threadIdx.x;
    const int r0 = blockIdx.x * ROWS_P;
    const int j = tid, head = j >> 5, lane = j & 31;

    for (int r = 0; r < ROWS_P; ++r) {
        int row = r0 + r, qi = row >> 5, b = row & 31;
        size_t base0 = (size_t)((b * NHEAD) + head) * Q_LEN + qi;
        size_t base1 = (size_t)(BATCH * NHEAD * Q_LEN) + base0;
        float inv = 1.0f / (g_L[base0] + g_L[base1]);
        float a0 = g_AO[base0 * HEAD_DIM + lane];
        float a1 = g_AO[base1 * HEAD_DIM + lane];
        s_att[r][j] = (a0 + a1) * inv;
    }
    __syncthreads();

    u64 accA[ROWS_P], accB[ROWS_P];
#pragma unroll
    for (int r = 0; r < ROWS_P; ++r) { accA[r] = accB[r] = 0ull; }
    const ulonglong2* wop = ((const ulonglong2*)g_WoT4) + j;
#pragma unroll 4
    for (int c4 = 0; c4 < D_MODEL / 4; ++c4) {
        ulonglong2 w4 = wop[(size_t)c4 * D_MODEL];
#pragma unroll
        for (int r = 0; r < ROWS_P; ++r) {
            ulonglong2 x = *(const ulonglong2*)(&s_att[r][4 * c4]);
            accA[r] = fma2(x.x, w4.x, accA[r]);
            accB[r] = fma2(x.y, w4.y, accB[r]);
        }
    }

    const float boj = bo[j];
    for (int r = 0; r < ROWS_P; ++r) {
        int row = r0 + r;
        s_y[r][j] = hsum2(accA[r]) + hsum2(accB[r]) + boj + tgt[(size_t)row * D_MODEL + j];
    }
    __syncthreads();

    {
        const int w = tid >> 5, ln = tid & 31;   // warp w handles row w (8 warps, 8 rows)
        float sval = 0.f, sq = 0.f;
        for (int c = ln; c < D_MODEL; c += 32) { float v = s_y[w][c]; sval += v; sq += v * v; }
#pragma unroll
        for (int off = 16; off > 0; off >>= 1) {
            sval += __shfl_xor_sync(0xffffffffu, sval, off);
            sq   += __shfl_xor_sync(0xffffffffu, sq, off);
        }
        if (ln == 0) {
            float mu = sval * (1.0f / D_MODEL);
            s_mu[w] = mu;
            s_rs[w] = rsqrtf(sq * (1.0f / D_MODEL) - mu * mu + 1e-5f);
        }
    }
    __syncthreads();

    const float g = ln_g[j], bb = ln_b[j];
    for (int r = 0; r < ROWS_P; ++r) {
        int row = r0 + r;
        out[(size_t)row * D_MODEL + j] = (s_y[r][j] - s_mu[r]) * s_rs[r] * g + bb;
    }
}

// ============================================================================
extern "C" void kernel_launch(void* const* d_in, const int* in_sizes, int n_in,
                              void* d_out, int out_size)
{
    const float* tgt  = (const float*)d_in[0];
    const float* text = (const float*)d_in[1];
    const float* qpos = (const float*)d_in[2];
    const float* oov  = (const float*)d_in[3];
    const float* Wq   = (const float*)d_in[4];
    const float* bq   = (const float*)d_in[5];
    const float* Wk   = (const float*)d_in[6];
    const float* bk   = (const float*)d_in[7];
    const float* Wv   = (const float*)d_in[8];
    const float* bv   = (const float*)d_in[9];
    const float* Wo   = (const float*)d_in[10];
    const float* bo   = (const float*)d_in[11];
    const float* lng  = (const float*)d_in[12];
    const float* lnb  = (const float*)d_in[13];
    const float* ls   = (const float*)d_in[14];
    float* out = (float*)d_out;

    // launch order chosen so attn_kernel is the 4th launch (matches the ncu
    // capture position observed last round).
    pack_all_kernel<<<512, 256>>>(Wq, Wk, Wv, Wo);                             // 1
    kv_kernel<<<dim3((T_LEN + ROWS_KV - 1) / ROWS_KV, 2), 256>>>(text, bk, bv, ls); // 2
    q_kernel<<<NROWS / ROWS_Q, 256>>>(tgt, qpos, bq);                          // 3

    const int att_smem = (Q_LEN * HEAD_DIM + 2 * TT * HEAD_DIM + Q_LEN * (TT + 1)) * (int)sizeof(float);
    cudaFuncSetAttribute(attn_kernel, cudaFuncAttributeMaxDynamicSharedMemorySize, att_smem);
    attn_kernel<<<dim3(NHEAD, BATCH, NSPLIT), 128, att_smem>>>(oov);           // 4 <- profiled

    proj_kernel<<<NROWS / ROWS_P, 256>>>(tgt, bo, lng, lnb, out);              // 5
}

// round 7
// speedup vs baseline: 1.6321x; 1.0526x over previous
#include <cuda_runtime.h>

#define D_MODEL 256
#define D_CLIP 768
#define NHEAD 8
#define HEAD_DIM 32
#define Q_LEN 100
#define BATCH 32
#define T_LEN 1203
#define NROWS (Q_LEN * BATCH)   // 3200
#define NSPLIT 4
#define TCHUNK 301              // ceil(1203/4); last chunk is 300
#define QSPLIT 2
#define QCH 50
#define LOG2E 1.4426950408889634f

typedef unsigned long long u64;

// ---- scratch (device globals; no allocation allowed) ----
__device__ float g_K[NHEAD * T_LEN * HEAD_DIM];   // normalized K * scale*(1-alpha_h)*log2e
__device__ float g_V[NHEAD * T_LEN * HEAD_DIM];
__device__ float g_Q[BATCH * NHEAD * Q_LEN * HEAD_DIM];            // normalized Q, [b][h][q][d]
__device__ float g_AO[NSPLIT * BATCH * NHEAD * Q_LEN * HEAD_DIM];  // unnormalized partial att out
__device__ float g_L[NSPLIT * BATCH * NHEAD * Q_LEN];              // partial exp-sums
// packed transposed weights: WT4[c4*256 + j] = float4 of W[j][4c4 .. 4c4+3]
__device__ float g_WqT4[D_MODEL * D_MODEL];
__device__ float g_WkT4[D_MODEL * D_CLIP];
__device__ float g_WvT4[D_MODEL * D_CLIP];
__device__ float g_WoT4[D_MODEL * D_MODEL];

// ---- packed fp32x2 helpers (Blackwell FFMA2) ----
__device__ __forceinline__ u64 pk2(float lo, float hi) {
    u64 r; asm("mov.b64 %0, {%1, %2};" : "=l"(r) : "f"(lo), "f"(hi)); return r;
}
__device__ __forceinline__ void unpk2(u64 v, float& lo, float& hi) {
    asm("mov.b64 {%0, %1}, %2;" : "=f"(lo), "=f"(hi) : "l"(v));
}
__device__ __forceinline__ u64 fma2(u64 a, u64 b, u64 c) {
    u64 d; asm("fma.rn.f32x2 %0, %1, %2, %3;" : "=l"(d) : "l"(a), "l"(b), "l"(c)); return d;
}
__device__ __forceinline__ u64 mul2(u64 a, u64 b) {
    u64 d; asm("mul.rn.f32x2 %0, %1, %2;" : "=l"(d) : "l"(a), "l"(b)); return d;
}
__device__ __forceinline__ u64 add2(u64 a, u64 b) {
    u64 d; asm("add.rn.f32x2 %0, %1, %2;" : "=l"(d) : "l"(a), "l"(b)); return d;
}
__device__ __forceinline__ float hsum2(u64 v) { float lo, hi; unpk2(v, lo, hi); return lo + hi; }
__device__ __forceinline__ float ex2(float x) {
    float r; asm("ex2.approx.f32 %0, %1;" : "=f"(r) : "f"(x)); return r;
}

// ============================================================================
// Kernel 0: pack ALL weights in one launch.
// ============================================================================
__global__ void pack_all_kernel(const float* __restrict__ Wq, const float* __restrict__ Wk,
                                const float* __restrict__ Wv, const float* __restrict__ Wo)
{
    const int idx = blockIdx.x * blockDim.x + threadIdx.x;   // grid covers 131072 exactly
    const float* src; float* dst; int n4, id;
    if (idx < 16384)       { src = Wq; dst = g_WqT4; n4 = 64;  id = idx; }
    else if (idx < 65536)  { src = Wk; dst = g_WkT4; n4 = 192; id = idx - 16384; }
    else if (idx < 114688) { src = Wv; dst = g_WvT4; n4 = 192; id = idx - 65536; }
    else                   { src = Wo; dst = g_WoT4; n4 = 64;  id = idx - 114688; }
    int j = id / n4, c4 = id - j * n4;
    float4 v = ((const float4*)src)[(size_t)j * n4 + c4];
    ((float4*)dst)[(size_t)c4 * D_MODEL + j] = v;
}

// ============================================================================
// Kernel 1: K or V projection (blockIdx.y selects matrix). K branch adds
// per-head l2norm and folds scale*(1-alpha_h)*log2e.
// ============================================================================
#define ROWS_KV 8
__global__ __launch_bounds__(256, 3) void kv_kernel(
    const float* __restrict__ text, const float* __restrict__ bk,
    const float* __restrict__ bv, const float* __restrict__ lsp)
{
    __shared__ float s_text[ROWS_KV][D_CLIP];   // 24 KB
    const int tid = threadIdx.x;
    const int t0 = blockIdx.x * ROWS_KV;
    const int isV = blockIdx.y;
    const int nrows = min(ROWS_KV, T_LEN - t0);

    for (int idx = tid; idx < ROWS_KV * (D_CLIP / 4); idx += 256) {
        int r = idx / (D_CLIP / 4);
        int c4 = idx % (D_CLIP / 4);
        float4 v = make_float4(0.f, 0.f, 0.f, 0.f);
        if (r < nrows) v = ((const float4*)(text + (size_t)(t0 + r) * D_CLIP))[c4];
        ((float4*)(&s_text[r][0]))[c4] = v;
    }
    __syncthreads();

    const int j = tid, head = j >> 5, lane = j & 31;
    u64 aA[ROWS_KV], aB[ROWS_KV];
#pragma unroll
    for (int r = 0; r < ROWS_KV; ++r) { aA[r] = aB[r] = 0ull; }

    const ulonglong2* wp = ((const ulonglong2*)(isV ? g_WvT4 : g_WkT4)) + j;
#pragma unroll 4
    for (int c4 = 0; c4 < D_CLIP / 4; ++c4) {
        ulonglong2 w4 = wp[(size_t)c4 * D_MODEL];
#pragma unroll
        for (int r = 0; r < ROWS_KV; ++r) {
            ulonglong2 x = *(const ulonglong2*)(&s_text[r][4 * c4]);
            aA[r] = fma2(x.x, w4.x, aA[r]);
            aB[r] = fma2(x.y, w4.y, aB[r]);
        }
    }

    if (isV) {
        const float bvj = bv[j];
        for (int r = 0; r < nrows; ++r) {
            int t = t0 + r;
            g_V[(head * T_LEN + t) * HEAD_DIM + lane] = hsum2(aA[r]) + hsum2(aB[r]) + bvj;
        }
    } else {
        const float scale = fminf(expf(lsp[0]), 100.0f);
        const float kfac = scale * (1.0f - (float)head * (1.0f / 7.0f)) * LOG2E;
        const float bkj = bk[j];
        for (int r = 0; r < nrows; ++r) {
            float kk = hsum2(aA[r]) + hsum2(aB[r]) + bkj;
            float ss = kk * kk;
#pragma unroll
            for (int off = 16; off > 0; off >>= 1) ss += __shfl_xor_sync(0xffffffffu, ss, off);
            float val = kk / fmaxf(sqrtf(ss), 1e-6f) * kfac;
            int t = t0 + r;
            g_K[(head * T_LEN + t) * HEAD_DIM + lane] = val;
        }
    }
}

// ============================================================================
// Kernel 2: Q projection + per-head l2norm, written as [b][h][q][d]
// ============================================================================
#define ROWS_Q 8
__global__ __launch_bounds__(256, 4) void q_kernel(
    const float* __restrict__ tgt, const float* __restrict__ qpos,
    const float* __restrict__ bq)
{
    __shared__ float s_in[ROWS_Q][D_MODEL];   // 8 KB
    const int tid = threadIdx.x;
    const int r0 = blockIdx.x * ROWS_Q;

    for (int idx = tid; idx < ROWS_Q * (D_MODEL / 4); idx += 256) {
        int r = idx >> 6, c4 = idx & 63;
        const float4 a = ((const float4*)(tgt  + (size_t)(r0 + r) * D_MODEL))[c4];
        const float4 p = ((const float4*)(qpos + (size_t)(r0 + r) * D_MODEL))[c4];
        ((float4*)(&s_in[r][0]))[c4] = make_float4(a.x + p.x, a.y + p.y, a.z + p.z, a.w + p.w);
    }
    __syncthreads();

    const int j = tid, head = j >> 5, lane = j & 31;
    u64 aA[ROWS_Q], aB[ROWS_Q];
#pragma unroll
    for (int r = 0; r < ROWS_Q; ++r) { aA[r] = aB[r] = 0ull; }

    const ulonglong2* wqp = ((const ulonglong2*)g_WqT4) + j;
#pragma unroll 4
    for (int c4 = 0; c4 < D_MODEL / 4; ++c4) {
        ulonglong2 w4 = wqp[(size_t)c4 * D_MODEL];
#pragma unroll
        for (int r = 0; r < ROWS_Q; ++r) {
            ulonglong2 x = *(const ulonglong2*)(&s_in[r][4 * c4]);
            aA[r] = fma2(x.x, w4.x, aA[r]);
            aB[r] = fma2(x.y, w4.y, aB[r]);
        }
    }

    const float bqj = bq[j];
    for (int r = 0; r < ROWS_Q; ++r) {
        float qq = hsum2(aA[r]) + hsum2(aB[r]) + bqj;
        float ss = qq * qq;
#pragma unroll
        for (int off = 16; off > 0; off >>= 1) ss += __shfl_xor_sync(0xffffffffu, ss, off);
        float val = qq / fmaxf(sqrtf(ss), 1e-6f);
        int row = r0 + r;
        int qi = row >> 5, b = row & 31;                 // row = qi*32 + b
        g_Q[(((b * NHEAD) + head) * Q_LEN + qi) * HEAD_DIM + lane] = val;
    }
}

// ============================================================================
// Kernel 3: attention, split over T (4-way) and Q (2-way). 128 threads.
// Lane-PAIR per query: even lane handles dims [0,16), odd lane dims [16,32).
// Dot halves combined with shfl.xor(1); both lanes compute p; each lane
// accumulates its 16-dim half of V. Halved registers -> 5 blocks/SM.
// Stores UNNORMALIZED output halves + exp-sum (even lane).
// ============================================================================
#define TT 64
#define SO_PITCH 68
__global__ __launch_bounds__(128, 5) void attn_kernel(const float* __restrict__ oov)
{
    const int h = blockIdx.x, b = blockIdx.y;
    const int s = blockIdx.z >> 1, qc = blockIdx.z & 1;
    const int t_begin = s * TCHUNK;
    const int t_end = min(T_LEN, t_begin + TCHUNK);
    const int qbase = qc * QCH;
    extern __shared__ float sm[];
    float* s_k = sm;                          // TT*32
    float* s_v = s_k + TT * HEAD_DIM;         // TT*32
    float* s_o = s_v + TT * HEAD_DIM;         // QCH*SO_PITCH (doubles as q-stage)
    const int tid = threadIdx.x;
    const int w = tid >> 5, l = tid & 31;
    const int q_local = w * 16 + (l >> 1);
    const int half = l & 1;
    const bool active = q_local < QCH;
    const int q_eff = min(q_local, QCH - 1);   // clamped for divergence-free compute

    // stage 50 Q rows into s_o region, pull into registers, then release
    {
        const float4* gq = (const float4*)(g_Q + ((size_t)(b * NHEAD + h) * Q_LEN + qbase) * HEAD_DIM);
        for (int idx = tid; idx < QCH * (HEAD_DIM / 4); idx += 128)
            ((float4*)s_o)[idx] = gq[idx];
    }
    __syncthreads();
    u64 q2[8];
    {
        const u64* qp = (const u64*)(s_o + q_eff * HEAD_DIM + half * 16);
#pragma unroll
        for (int jj = 0; jj < 8; ++jj) q2[jj] = qp[jj];
    }
    __syncthreads();

    u64 ao[8];
#pragma unroll
    for (int jj = 0; jj < 8; ++jj) ao[jj] = 0ull;
    float lsum = 0.f;

    const float ap = (float)h * (1.0f / 7.0f) * LOG2E;   // alpha * log2e
    const bool use_qk = (h != NHEAD - 1);
    const bool use_ov = (h != 0);
    const float* oov_b = oov + ((size_t)b * Q_LEN + qbase) * T_LEN;

    for (int t0 = t_begin; t0 < t_end; t0 += TT) {
        const int tt = min(TT, t_end - t0);
        __syncthreads();
        {
            const float4* gk = (const float4*)(g_K + (size_t)(h * T_LEN + t0) * HEAD_DIM);
            const float4* gv = (const float4*)(g_V + (size_t)(h * T_LEN + t0) * HEAD_DIM);
            for (int idx = tid; idx < tt * (HEAD_DIM / 4); idx += 128) {
                ((float4*)s_k)[idx] = gk[idx];
                ((float4*)s_v)[idx] = gv[idx];
            }
            if (use_ov) {
                const int tcol = tid & 63;
                const int rh = tid >> 6;             // 0/1 -> rows [0,25)/[25,50)
                if (tcol < tt) {
                    const float* src = oov_b + (size_t)(rh * 25) * T_LEN + t0 + tcol;
                    float* dst = s_o + (rh * 25) * SO_PITCH + tcol;
#pragma unroll 5
                    for (int r = 0; r < 25; ++r)
                        dst[r * SO_PITCH] = ap * src[(size_t)r * T_LEN];
                }
            }
        }
        __syncthreads();
        {
            const float* so = s_o + q_eff * SO_PITCH;
#pragma unroll 2
            for (int t = 0; t < tt; ++t) {
                float lg = 0.f;
                if (use_qk) {
                    const ulonglong2* kp = (const ulonglong2*)(s_k + t * HEAD_DIM + half * 16);
                    ulonglong2 ka = kp[0], kb = kp[1], kc = kp[2], kd = kp[3];
                    u64 a0 = mul2(q2[0], ka.x);
                    u64 a1 = mul2(q2[1], ka.y);
                    u64 a2 = mul2(q2[2], kb.x);
                    u64 a3 = mul2(q2[3], kb.y);
                    a0 = fma2(q2[4], kc.x, a0);
                    a1 = fma2(q2[5], kc.y, a1);
                    a2 = fma2(q2[6], kd.x, a2);
                    a3 = fma2(q2[7], kd.y, a3);
                    a0 = add2(a0, a1); a2 = add2(a2, a3); a0 = add2(a0, a2);
                    float part = hsum2(a0);
                    lg = part + __shfl_xor_sync(0xffffffffu, part, 1);
                }
                if (use_ov) lg += so[t];
                const float p = ex2(lg);
                lsum += p;
                const u64 p2 = pk2(p, p);
                const ulonglong2* vp = (const ulonglong2*)(s_v + t * HEAD_DIM + half * 16);
                ulonglong2 v0 = vp[0], v1 = vp[1], v2 = vp[2], v3 = vp[3];
                ao[0] = fma2(p2, v0.x, ao[0]);
                ao[1] = fma2(p2, v0.y, ao[1]);
                ao[2] = fma2(p2, v1.x, ao[2]);
                ao[3] = fma2(p2, v1.y, ao[3]);
                ao[4] = fma2(p2, v2.x, ao[4]);
                ao[5] = fma2(p2, v2.y, ao[5]);
                ao[6] = fma2(p2, v3.x, ao[6]);
                ao[7] = fma2(p2, v3.y, ao[7]);
            }
        }
    }

    if (active) {
        const size_t base = ((size_t)((s * BATCH + b) * NHEAD + h) * Q_LEN + qbase + q_local);
        if (half == 0) g_L[base] = lsum;
        float* dst = g_AO + base * HEAD_DIM + half * 16;
#pragma unroll
        for (int jj = 0; jj < 8; ++jj) {
            float lo, hi; unpk2(ao[jj], lo, hi);
            dst[2 * jj]     = lo;
            dst[2 * jj + 1] = hi;
        }
    }
}

// ============================================================================
// Kernel 4: combine 4 attention splits + output projection + residual + LN
// ============================================================================
#define ROWS_P 8
#define SSTRIDE (BATCH * NHEAD * Q_LEN)
__global__ __launch_bounds__(256, 4) void proj_kernel(
    const float* __restrict__ tgt, const float* __restrict__ bo,
    const float* __restrict__ ln_g, const float* __restrict__ ln_b, float* __restrict__ out)
{
    __shared__ float s_att[ROWS_P][D_MODEL];
    __shared__ float s_y[ROWS_P][D_MODEL];
    __shared__ float s_mu[ROWS_P], s_rs[ROWS_P];
    const int tid = threadIdx.x;
    const int r0 = blockIdx.x * ROWS_P;
    const int j = tid, head = j >> 5, lane = j & 31;

    for (int r = 0; r < ROWS_P; ++r) {
        int row = r0 + r, qi = row >> 5, b = row & 31;
        size_t base = (size_t)((b * NHEAD) + head) * Q_LEN + qi;
        float lsum = g_L[base] + g_L[base + SSTRIDE] + g_L[base + 2 * SSTRIDE] + g_L[base + 3 * SSTRIDE];
        float a = g_AO[base * HEAD_DIM + lane]
                + g_AO[(base + SSTRIDE) * HEAD_DIM + lane]
                + g_AO[(base + 2 * (size_t)SSTRIDE) * HEAD_DIM + lane]
                + g_AO[(base + 3 * (size_t)SSTRIDE) * HEAD_DIM + lane];
        s_att[r][j] = a / lsum;
    }
    __syncthreads();

    u64 accA[ROWS_P], accB[ROWS_P];
#pragma unroll
    for (int r = 0; r < ROWS_P; ++r) { accA[r] = accB[r] = 0ull; }
    const ulonglong2* wop = ((const ulonglong2*)g_WoT4) + j;
#pragma unroll 4
    for (int c4 = 0; c4 < D_MODEL / 4; ++c4) {
        ulonglong2 w4 = wop[(size_t)c4 * D_MODEL];
#pragma unroll
        for (int r = 0; r < ROWS_P; ++r) {
            ulonglong2 x = *(const ulonglong2*)(&s_att[r][4 * c4]);
            accA[r] = fma2(x.x, w4.x, accA[r]);
            accB[r] = fma2(x.y, w4.y, accB[r]);
        }
    }

    const float boj = bo[j];
    for (int r = 0; r < ROWS_P; ++r) {
        int row = r0 + r;
        s_y[r][j] = hsum2(accA[r]) + hsum2(accB[r]) + boj + tgt[(size_t)row * D_MODEL + j];
    }
    __syncthreads();

    {
        const int w = tid >> 5, ln = tid & 31;   // warp w handles row w (8 warps, 8 rows)
        float sval = 0.f, sq = 0.f;
        for (int c = ln; c < D_MODEL; c += 32) { float v = s_y[w][c]; sval += v; sq += v * v; }
#pragma unroll
        for (int off = 16; off > 0; off >>= 1) {
            sval += __shfl_xor_sync(0xffffffffu, sval, off);
            sq   += __shfl_xor_sync(0xffffffffu, sq, off);
        }
        if (ln == 0) {
            float mu = sval * (1.0f / D_MODEL);
            s_mu[w] = mu;
            s_rs[w] = rsqrtf(sq * (1.0f / D_MODEL) - mu * mu + 1e-5f);
        }
    }
    __syncthreads();

    const float g = ln_g[j], bb = ln_b[j];
    for (int r = 0; r < ROWS_P; ++r) {
        int row = r0 + r;
        out[(size_t)row * D_MODEL + j] = (s_y[r][j] - s_mu[r]) * s_rs[r] * g + bb;
    }
}

// ============================================================================
extern "C" void kernel_launch(void* const* d_in, const int* in_sizes, int n_in,
                              void* d_out, int out_size)
{
    const float* tgt  = (const float*)d_in[0];
    const float* text = (const float*)d_in[1];
    const float* qpos = (const float*)d_in[2];
    const float* oov  = (const float*)d_in[3];
    const float* Wq   = (const float*)d_in[4];
    const float* bq   = (const float*)d_in[5];
    const float* Wk   = (const float*)d_in[6];
    const float* bk   = (const float*)d_in[7];
    const float* Wv   = (const float*)d_in[8];
    const float* bv   = (const float*)d_in[9];
    const float* Wo   = (const float*)d_in[10];
    const float* bo   = (const float*)d_in[11];
    const float* lng  = (const float*)d_in[12];
    const float* lnb  = (const float*)d_in[13];
    const float* ls   = (const float*)d_in[14];
    float* out = (float*)d_out;

    // attn_kernel is the 4th launch (ncu capture position)
    pack_all_kernel<<<512, 256>>>(Wq, Wk, Wv, Wo);                             // 1
    kv_kernel<<<dim3((T_LEN + ROWS_KV - 1) / ROWS_KV, 2), 256>>>(text, bk, bv, ls); // 2
    q_kernel<<<NROWS / ROWS_Q, 256>>>(tgt, qpos, bq);                          // 3

    const int att_smem = (2 * TT * HEAD_DIM + QCH * SO_PITCH) * (int)sizeof(float);
    cudaFuncSetAttribute(attn_kernel, cudaFuncAttributeMaxDynamicSharedMemorySize, att_smem);
    attn_kernel<<<dim3(NHEAD, BATCH, NSPLIT * QSPLIT), 128, att_smem>>>(oov);  // 4 <- profiled

    proj_kernel<<<NROWS / ROWS_P, 256>>>(tgt, bo, lng, lnb, out);              // 5
}

// round 9
// speedup vs baseline: 1.6358x; 1.0023x over previous
#include <cuda_runtime.h>
#include <cuda_fp16.h>

#define D_MODEL 256
#define D_CLIP 768
#define NHEAD 8
#define HEAD_DIM 32
#define Q_LEN 100
#define BATCH 32
#define T_LEN 1203
#define T_PAD 1216
#define NROWS (Q_LEN * BATCH)   // 3200
#define LOG2E 1.4426950408889634f
#define TT 64
#define VT_PITCH 72             // 64 + 8 halfs: conflict-free V^T reads

typedef unsigned long long u64;
typedef unsigned int u32;

// ---- scratch (device globals) ----
__device__ __half g_Khi[NHEAD * T_PAD * HEAD_DIM];   // K * scale*(1-a_h)*log2e, split hi
__device__ __half g_Klo[NHEAD * T_PAD * HEAD_DIM];
__device__ __half g_Vthi[NHEAD * HEAD_DIM * T_PAD];  // V transposed [h][d][t], split
__device__ __half g_Vtlo[NHEAD * HEAD_DIM * T_PAD];
__device__ __half g_Qhi[BATCH * NHEAD * Q_LEN * HEAD_DIM];
__device__ __half g_Qlo[BATCH * NHEAD * Q_LEN * HEAD_DIM];
__device__ float g_AT[BATCH * NHEAD * Q_LEN * HEAD_DIM];  // normalized attn out
// packed transposed weights
__device__ float g_WqT4[D_MODEL * D_MODEL];
__device__ float g_WkT4[D_MODEL * D_CLIP];
__device__ float g_WvT4[D_MODEL * D_CLIP];
__device__ float g_WoT4[D_MODEL * D_MODEL];

// ---- packed fp32x2 helpers ----
__device__ __forceinline__ void unpk2(u64 v, float& lo, float& hi) {
    asm("mov.b64 {%0, %1}, %2;" : "=f"(lo), "=f"(hi) : "l"(v));
}
__device__ __forceinline__ u64 fma2(u64 a, u64 b, u64 c) {
    u64 d; asm("fma.rn.f32x2 %0, %1, %2, %3;" : "=l"(d) : "l"(a), "l"(b), "l"(c)); return d;
}
__device__ __forceinline__ float hsum2(u64 v) { float lo, hi; unpk2(v, lo, hi); return lo + hi; }
__device__ __forceinline__ float ex2(float x) {
    float r; asm("ex2.approx.f32 %0, %1;" : "=f"(r) : "f"(x)); return r;
}
// pack two f32 -> f16x2 (lo -> low half)
__device__ __forceinline__ u32 f2h2(float flo, float fhi) {
    u32 r; asm("cvt.rn.f16x2.f32 %0, %1, %2;" : "=r"(r) : "f"(fhi), "f"(flo)); return r;
}
__device__ __forceinline__ float2 h22f2(u32 h) {
    __half2 hh = *reinterpret_cast<__half2*>(&h);
    return __half22float2(hh);
}
__device__ __forceinline__ void mma16816(float* d, const u32* a, u32 b0, u32 b1) {
    asm volatile("mma.sync.aligned.m16n8k16.row.col.f32.f16.f16.f32 "
        "{%0,%1,%2,%3}, {%4,%5,%6,%7}, {%8,%9}, {%0,%1,%2,%3};"
        : "+f"(d[0]), "+f"(d[1]), "+f"(d[2]), "+f"(d[3])
        : "r"(a[0]), "r"(a[1]), "r"(a[2]), "r"(a[3]), "r"(b0), "r"(b1));
}
__device__ __forceinline__ void split16(float v, __half& hi, __half& lo) {
    hi = __float2half_rn(v);
    lo = __float2half_rn(v - __half2float(hi));
}

// ============================================================================
// Kernel 0: pack weights + zero-fill K/V padding rows (t in [1203,1216)).
// ============================================================================
__global__ void pack_all_kernel(const float* __restrict__ Wq, const float* __restrict__ Wk,
                                const float* __restrict__ Wv, const float* __restrict__ Wo)
{
    const int idx = blockIdx.x * blockDim.x + threadIdx.x;
    if (idx < 131072) {
        const float* src; float* dst; int n4, id;
        if (idx < 16384)       { src = Wq; dst = g_WqT4; n4 = 64;  id = idx; }
        else if (idx < 65536)  { src = Wk; dst = g_WkT4; n4 = 192; id = idx - 16384; }
        else if (idx < 114688) { src = Wv; dst = g_WvT4; n4 = 192; id = idx - 65536; }
        else                   { src = Wo; dst = g_WoT4; n4 = 64;  id = idx - 114688; }
        int j = id / n4, c4 = id - j * n4;
        float4 v = ((const float4*)src)[(size_t)j * n4 + c4];
        ((float4*)dst)[(size_t)c4 * D_MODEL + j] = v;
    } else {
        int p = idx - 131072;                 // 13312 pad halfs (x2 arrays each)
        if (p < 6656) {
            int a = p / 3328, r = p % 3328;   // K pads: h, t in [1203,1216), d
            int h = r / 416, rr = r % 416;
            int t = T_LEN + rr / 32, d = rr % 32;
            __half* dst = a ? g_Klo : g_Khi;
            dst[((size_t)h * T_PAD + t) * 32 + d] = __half(0.0f);
        } else if (p < 13312) {
            int q = p - 6656;
            int a = q / 3328, r = q % 3328;   // Vt pads: row = h*32+d, t
            int row = r / 13, t = T_LEN + r % 13;
            __half* dst = a ? g_Vtlo : g_Vthi;
            dst[(size_t)row * T_PAD + t] = __half(0.0f);
        }
    }
}

// ============================================================================
// Kernel 1: K or V projection. K: l2norm + fold scale*(1-a_h)*log2e, split fp16.
// V: split fp16, stored transposed [h][d][t].
// ============================================================================
#define ROWS_KV 8
__global__ __launch_bounds__(256, 3) void kv_kernel(
    const float* __restrict__ text, const float* __restrict__ bk,
    const float* __restrict__ bv, const float* __restrict__ lsp)
{
    __shared__ float s_text[ROWS_KV][D_CLIP];   // 24 KB
    const int tid = threadIdx.x;
    const int t0 = blockIdx.x * ROWS_KV;
    const int isV = blockIdx.y;
    const int nrows = min(ROWS_KV, T_LEN - t0);

    for (int idx = tid; idx < ROWS_KV * (D_CLIP / 4); idx += 256) {
        int r = idx / (D_CLIP / 4);
        int c4 = idx % (D_CLIP / 4);
        float4 v = make_float4(0.f, 0.f, 0.f, 0.f);
        if (r < nrows) v = ((const float4*)(text + (size_t)(t0 + r) * D_CLIP))[c4];
        ((float4*)(&s_text[r][0]))[c4] = v;
    }
    __syncthreads();

    const int j = tid, head = j >> 5, lane = j & 31;
    u64 aA[ROWS_KV], aB[ROWS_KV];
#pragma unroll
    for (int r = 0; r < ROWS_KV; ++r) { aA[r] = aB[r] = 0ull; }

    const ulonglong2* wp = ((const ulonglong2*)(isV ? g_WvT4 : g_WkT4)) + j;
#pragma unroll 4
    for (int c4 = 0; c4 < D_CLIP / 4; ++c4) {
        ulonglong2 w4 = wp[(size_t)c4 * D_MODEL];
#pragma unroll
        for (int r = 0; r < ROWS_KV; ++r) {
            ulonglong2 x = *(const ulonglong2*)(&s_text[r][4 * c4]);
            aA[r] = fma2(x.x, w4.x, aA[r]);
            aB[r] = fma2(x.y, w4.y, aB[r]);
        }
    }

    if (isV) {
        const float bvj = bv[j];
        for (int r = 0; r < nrows; ++r) {
            int t = t0 + r;
            float v = hsum2(aA[r]) + hsum2(aB[r]) + bvj;
            __half hi, lo; split16(v, hi, lo);
            size_t o = (size_t)(head * 32 + lane) * T_PAD + t;
            g_Vthi[o] = hi; g_Vtlo[o] = lo;
        }
    } else {
        const float scale = fminf(expf(lsp[0]), 100.0f);
        const float kfac = scale * (1.0f - (float)head * (1.0f / 7.0f)) * LOG2E;
        const float bkj = bk[j];
        for (int r = 0; r < nrows; ++r) {
            float kk = hsum2(aA[r]) + hsum2(aB[r]) + bkj;
            float ss = kk * kk;
#pragma unroll
            for (int off = 16; off > 0; off >>= 1) ss += __shfl_xor_sync(0xffffffffu, ss, off);
            float val = kk / fmaxf(sqrtf(ss), 1e-6f) * kfac;
            __half hi, lo; split16(val, hi, lo);
            size_t o = ((size_t)head * T_PAD + t0 + r) * 32 + lane;
            g_Khi[o] = hi; g_Klo[o] = lo;
        }
    }
}

// ============================================================================
// Kernel 2: Q projection + l2norm, split fp16, [b][h][q][d]
// ============================================================================
#define ROWS_Q 8
__global__ __launch_bounds__(256, 4) void q_kernel(
    const float* __restrict__ tgt, const float* __restrict__ qpos,
    const float* __restrict__ bq)
{
    __shared__ float s_in[ROWS_Q][D_MODEL];
    const int tid = threadIdx.x;
    const int r0 = blockIdx.x * ROWS_Q;

    for (int idx = tid; idx < ROWS_Q * (D_MODEL / 4); idx += 256) {
        int r = idx >> 6, c4 = idx & 63;
        const float4 a = ((const float4*)(tgt  + (size_t)(r0 + r) * D_MODEL))[c4];
        const float4 p = ((const float4*)(qpos + (size_t)(r0 + r) * D_MODEL))[c4];
        ((float4*)(&s_in[r][0]))[c4] = make_float4(a.x + p.x, a.y + p.y, a.z + p.z, a.w + p.w);
    }
    __syncthreads();

    const int j = tid, head = j >> 5, lane = j & 31;
    u64 aA[ROWS_Q], aB[ROWS_Q];
#pragma unroll
    for (int r = 0; r < ROWS_Q; ++r) { aA[r] = aB[r] = 0ull; }

    const ulonglong2* wqp = ((const ulonglong2*)g_WqT4) + j;
#pragma unroll 4
    for (int c4 = 0; c4 < D_MODEL / 4; ++c4) {
        ulonglong2 w4 = wqp[(size_t)c4 * D_MODEL];
#pragma unroll
        for (int r = 0; r < ROWS_Q; ++r) {
            ulonglong2 x = *(const ulonglong2*)(&s_in[r][4 * c4]);
            aA[r] = fma2(x.x, w4.x, aA[r]);
            aB[r] = fma2(x.y, w4.y, aB[r]);
        }
    }

    const float bqj = bq[j];
    for (int r = 0; r < ROWS_Q; ++r) {
        float qq = hsum2(aA[r]) + hsum2(aB[r]) + bqj;
        float ss = qq * qq;
#pragma unroll
        for (int off = 16; off > 0; off >>= 1) ss += __shfl_xor_sync(0xffffffffu, ss, off);
        float val = qq / fmaxf(sqrtf(ss), 1e-6f);
        int row = r0 + r;
        int qi = row >> 5, b = row & 31;
        __half hi, lo; split16(val, hi, lo);
        size_t o = ((size_t)((b * NHEAD) + head) * Q_LEN + qi) * HEAD_DIM + lane;
        g_Qhi[o] = hi; g_Qlo[o] = lo;
    }
}

// ============================================================================
// Kernel 3: HMMA flash attention. Block = (h, b, qhalf); 4 warps x m16 queries.
// Split-fp16 (hi+lo) 3-MMA GEMMs for QK^T and PV; online softmax in log2.
// ============================================================================
__global__ __launch_bounds__(128, 4) void attn_kernel(const float* __restrict__ oov)
{
    const int h = blockIdx.x, b = blockIdx.y, qc = blockIdx.z;
    const int tid = threadIdx.x;
    const int warp = tid >> 5, lane = tid & 31;
    const int g = lane >> 2, c = lane & 3;
    const int q0 = qc * 64 + warp * 16;
    const int r0 = min(q0 + g, Q_LEN - 1);
    const int r1 = min(q0 + g + 8, Q_LEN - 1);

    __shared__ __align__(16) __half sKhi[64 * 32], sKlo[64 * 32];
    __shared__ __align__(16) __half sVhi[32 * VT_PITCH], sVlo[32 * VT_PITCH];

    // ---- Q a-frags (2 ksteps x 4 regs, hi+lo) ----
    u32 qa_hi[2][4], qa_lo[2][4];
    {
        const __half* Qh = g_Qhi + (size_t)(b * NHEAD + h) * Q_LEN * HEAD_DIM;
        const __half* Ql = g_Qlo + (size_t)(b * NHEAD + h) * Q_LEN * HEAD_DIM;
#pragma unroll
        for (int ks = 0; ks < 2; ++ks) {
            int col = 16 * ks + 2 * c;
            qa_hi[ks][0] = *(const u32*)&Qh[r0 * 32 + col];
            qa_hi[ks][1] = *(const u32*)&Qh[r1 * 32 + col];
            qa_hi[ks][2] = *(const u32*)&Qh[r0 * 32 + col + 8];
            qa_hi[ks][3] = *(const u32*)&Qh[r1 * 32 + col + 8];
            qa_lo[ks][0] = *(const u32*)&Ql[r0 * 32 + col];
            qa_lo[ks][1] = *(const u32*)&Ql[r1 * 32 + col];
            qa_lo[ks][2] = *(const u32*)&Ql[r0 * 32 + col + 8];
            qa_lo[ks][3] = *(const u32*)&Ql[r1 * 32 + col + 8];
        }
    }

    float O[4][4];
#pragma unroll
    for (int dt = 0; dt < 4; ++dt)
#pragma unroll
        for (int e = 0; e < 4; ++e) O[dt][e] = 0.f;
    float m0 = -1e30f, m1 = -1e30f, l0 = 0.f, l1 = 0.f;

    const float ap = (float)h * (1.0f / 7.0f) * LOG2E;
    const bool use_qk = (h != NHEAD - 1);
    const bool use_ov = (h != 0);
    const float* oovA = oov + ((size_t)b * Q_LEN + r0) * T_LEN;
    const float* oovB = oov + ((size_t)b * Q_LEN + r1) * T_LEN;

    const int kbase = g * 32 + 2 * c;
    const int vbase = g * VT_PITCH + 2 * c;

    for (int t0 = 0; t0 < T_LEN; t0 += TT) {
        __syncthreads();
        // ---- stage chunk: K (hi/lo) rows t0..t0+63, V^T (hi/lo) cols ----
        {
            const float4* srcKh = (const float4*)(g_Khi + ((size_t)h * T_PAD + t0) * 32);
            const float4* srcKl = (const float4*)(g_Klo + ((size_t)h * T_PAD + t0) * 32);
            ((float4*)sKhi)[tid] = srcKh[tid];
            ((float4*)sKhi)[tid + 128] = srcKh[tid + 128];
            ((float4*)sKlo)[tid] = srcKl[tid];
            ((float4*)sKlo)[tid + 128] = srcKl[tid + 128];
            const float4* srcVh = (const float4*)g_Vthi;
            const float4* srcVl = (const float4*)g_Vtlo;
            int u1 = tid, u2 = tid + 128;
            int d1 = u1 >> 3, s1 = u1 & 7, d2 = u2 >> 3, s2 = u2 & 7;
            ((float4*)sVhi)[d1 * 9 + s1] = srcVh[(size_t)(h * 32 + d1) * (T_PAD / 8) + (t0 >> 3) + s1];
            ((float4*)sVhi)[d2 * 9 + s2] = srcVh[(size_t)(h * 32 + d2) * (T_PAD / 8) + (t0 >> 3) + s2];
            ((float4*)sVlo)[d1 * 9 + s1] = srcVl[(size_t)(h * 32 + d1) * (T_PAD / 8) + (t0 >> 3) + s1];
            ((float4*)sVlo)[d2 * 9 + s2] = srcVl[(size_t)(h * 32 + d2) * (T_PAD / 8) + (t0 >> 3) + s2];
        }
        __syncthreads();

        // ---- S = Q K^T (8 n-tiles of 8 keys) ----
        float s[8][4];
#pragma unroll
        for (int j = 0; j < 8; ++j)
#pragma unroll
            for (int e = 0; e < 4; ++e) s[j][e] = 0.f;

        if (use_qk) {
#pragma unroll
            for (int j = 0; j < 8; ++j) {
#pragma unroll
                for (int ks = 0; ks < 2; ++ks) {
                    const __half* kh = sKhi + j * 256 + kbase + 16 * ks;
                    const __half* kl = sKlo + j * 256 + kbase + 16 * ks;
                    u32 bh0 = *(const u32*)kh;
                    u32 bh1 = *(const u32*)(kh + 8);
                    u32 bl0 = *(const u32*)kl;
                    u32 bl1 = *(const u32*)(kl + 8);
                    mma16816(s[j], qa_hi[ks], bh0, bh1);
                    mma16816(s[j], qa_hi[ks], bl0, bl1);
                    mma16816(s[j], qa_lo[ks], bh0, bh1);
                }
            }
        }
        if (use_ov) {
#pragma unroll
            for (int j = 0; j < 8; ++j) {
                // per-element clamp: position t may be valid while t+1 is not.
                int t = t0 + 8 * j + 2 * c;
                int c0 = min(t, T_LEN - 1);
                int c1 = min(t + 1, T_LEN - 1);
                s[j][0] = fmaf(ap, oovA[c0], s[j][0]);
                s[j][1] = fmaf(ap, oovA[c1], s[j][1]);
                s[j][2] = fmaf(ap, oovB[c0], s[j][2]);
                s[j][3] = fmaf(ap, oovB[c1], s[j][3]);
            }
        }
        if (t0 + TT > T_LEN) {
#pragma unroll
            for (int j = 0; j < 8; ++j) {
                int t = t0 + 8 * j + 2 * c;
                if (t >= T_LEN)     { s[j][0] = -1e30f; s[j][2] = -1e30f; }
                if (t + 1 >= T_LEN) { s[j][1] = -1e30f; s[j][3] = -1e30f; }
            }
        }

        // ---- online softmax (log2 domain) ----
        float cm0 = s[0][0], cm1 = s[0][2];
#pragma unroll
        for (int j = 0; j < 8; ++j) {
            cm0 = fmaxf(cm0, fmaxf(s[j][0], s[j][1]));
            cm1 = fmaxf(cm1, fmaxf(s[j][2], s[j][3]));
        }
        cm0 = fmaxf(cm0, __shfl_xor_sync(0xffffffffu, cm0, 1));
        cm0 = fmaxf(cm0, __shfl_xor_sync(0xffffffffu, cm0, 2));
        cm1 = fmaxf(cm1, __shfl_xor_sync(0xffffffffu, cm1, 1));
        cm1 = fmaxf(cm1, __shfl_xor_sync(0xffffffffu, cm1, 2));
        float nm0 = fmaxf(m0, cm0), nm1 = fmaxf(m1, cm1);
        float rs0 = ex2(m0 - nm0), rs1 = ex2(m1 - nm1);
        m0 = nm0; m1 = nm1;
        l0 *= rs0; l1 *= rs1;
#pragma unroll
        for (int dt = 0; dt < 4; ++dt) {
            O[dt][0] *= rs0; O[dt][1] *= rs0;
            O[dt][2] *= rs1; O[dt][3] *= rs1;
        }
#pragma unroll
        for (int j = 0; j < 8; ++j) {
            s[j][0] = ex2(s[j][0] - m0);
            s[j][1] = ex2(s[j][1] - m0);
            s[j][2] = ex2(s[j][2] - m1);
            s[j][3] = ex2(s[j][3] - m1);
            l0 += s[j][0] + s[j][1];
            l1 += s[j][2] + s[j][3];
        }

        // ---- O += P V, per kstep: build P a-frags (hi/lo), then 4 d-tiles ----
#pragma unroll
        for (int ks = 0; ks < 4; ++ks) {
            const int j0 = 2 * ks, j1 = 2 * ks + 1;
            u32 pa_hi[4], pa_lo[4];
            pa_hi[0] = f2h2(s[j0][0], s[j0][1]);
            pa_hi[1] = f2h2(s[j0][2], s[j0][3]);
            pa_hi[2] = f2h2(s[j1][0], s[j1][1]);
            pa_hi[3] = f2h2(s[j1][2], s[j1][3]);
#pragma unroll
            for (int e = 0; e < 4; ++e) {
                const int jj = (e < 2) ? j0 : j1;
                const int base = (e & 1) ? 2 : 0;
                float2 hf = h22f2(pa_hi[e]);
                pa_lo[e] = f2h2(s[jj][base] - hf.x, s[jj][base + 1] - hf.y);
            }
#pragma unroll
            for (int dt = 0; dt < 4; ++dt) {
                const __half* vh = sVhi + dt * 8 * VT_PITCH + vbase + 16 * ks;
                const __half* vl = sVlo + dt * 8 * VT_PITCH + vbase + 16 * ks;
                u32 bh0 = *(const u32*)vh;
                u32 bh1 = *(const u32*)(vh + 8);
                u32 bl0 = *(const u32*)vl;
                u32 bl1 = *(const u32*)(vl + 8);
                mma16816(O[dt], pa_hi, bh0, bh1);
                mma16816(O[dt], pa_hi, bl0, bl1);
                mma16816(O[dt], pa_lo, bh0, bh1);
            }
        }
    }

    // ---- epilogue: reduce l across quad, normalize, store ----
    l0 += __shfl_xor_sync(0xffffffffu, l0, 1);
    l0 += __shfl_xor_sync(0xffffffffu, l0, 2);
    l1 += __shfl_xor_sync(0xffffffffu, l1, 1);
    l1 += __shfl_xor_sync(0xffffffffu, l1, 2);
    const float inv0 = 1.0f / l0, inv1 = 1.0f / l1;
    float* dstBase = g_AT + (size_t)(b * NHEAD + h) * Q_LEN * HEAD_DIM;
    if (q0 + g < Q_LEN) {
        float* d0 = dstBase + (size_t)(q0 + g) * HEAD_DIM + 2 * c;
#pragma unroll
        for (int dt = 0; dt < 4; ++dt)
            *(float2*)(d0 + 8 * dt) = make_float2(O[dt][0] * inv0, O[dt][1] * inv0);
    }
    if (q0 + g + 8 < Q_LEN) {
        float* d1 = dstBase + (size_t)(q0 + g + 8) * HEAD_DIM + 2 * c;
#pragma unroll
        for (int dt = 0; dt < 4; ++dt)
            *(float2*)(d1 + 8 * dt) = make_float2(O[dt][2] * inv1, O[dt][3] * inv1);
    }
}

// ============================================================================
// Kernel 4: output projection + residual + LayerNorm
// ============================================================================
#define ROWS_P 8
__global__ __launch_bounds__(256, 4) void proj_kernel(
    const float* __restrict__ tgt, const float* __restrict__ bo,
    const float* __restrict__ ln_g, const float* __restrict__ ln_b, float* __restrict__ out)
{
    __shared__ float s_att[ROWS_P][D_MODEL];
    __shared__ float s_y[ROWS_P][D_MODEL];
    __shared__ float s_mu[ROWS_P], s_rs[ROWS_P];
    const int tid = threadIdx.x;
    const int r0 = blockIdx.x * ROWS_P;
    const int j = tid, head = j >> 5, lane = j & 31;

    for (int r = 0; r < ROWS_P; ++r) {
        int row = r0 + r, qi = row >> 5, b = row & 31;
        s_att[r][j] = g_AT[((size_t)((b * NHEAD) + head) * Q_LEN + qi) * HEAD_DIM + lane];
    }
    __syncthreads();

    u64 accA[ROWS_P], accB[ROWS_P];
#pragma unroll
    for (int r = 0; r < ROWS_P; ++r) { accA[r] = accB[r] = 0ull; }
    const ulonglong2* wop = ((const ulonglong2*)g_WoT4) + j;
#pragma unroll 4
    for (int c4 = 0; c4 < D_MODEL / 4; ++c4) {
        ulonglong2 w4 = wop[(size_t)c4 * D_MODEL];
#pragma unroll
        for (int r = 0; r < ROWS_P; ++r) {
            ulonglong2 x = *(const ulonglong2*)(&s_att[r][4 * c4]);
            accA[r] = fma2(x.x, w4.x, accA[r]);
            accB[r] = fma2(x.y, w4.y, accB[r]);
        }
    }

    const float boj = bo[j];
    for (int r = 0; r < ROWS_P; ++r) {
        int row = r0 + r;
        s_y[r][j] = hsum2(accA[r]) + hsum2(accB[r]) + boj + tgt[(size_t)row * D_MODEL + j];
    }
    __syncthreads();

    {
        const int w = tid >> 5, ln = tid & 31;
        float sval = 0.f, sq = 0.f;
        for (int cc = ln; cc < D_MODEL; cc += 32) { float v = s_y[w][cc]; sval += v; sq += v * v; }
#pragma unroll
        for (int off = 16; off > 0; off >>= 1) {
            sval += __shfl_xor_sync(0xffffffffu, sval, off);
            sq   += __shfl_xor_sync(0xffffffffu, sq, off);
        }
        if (ln == 0) {
            float mu = sval * (1.0f / D_MODEL);
            s_mu[w] = mu;
            s_rs[w] = rsqrtf(sq * (1.0f / D_MODEL) - mu * mu + 1e-5f);
        }
    }
    __syncthreads();

    const float gg = ln_g[j], bb = ln_b[j];
    for (int r = 0; r < ROWS_P; ++r) {
        int row = r0 + r;
        out[(size_t)row * D_MODEL + j] = (s_y[r][j] - s_mu[r]) * s_rs[r] * gg + bb;
    }
}

// ============================================================================
extern "C" void kernel_launch(void* const* d_in, const int* in_sizes, int n_in,
                              void* d_out, int out_size)
{
    const float* tgt  = (const float*)d_in[0];
    const float* text = (const float*)d_in[1];
    const float* qpos = (const float*)d_in[2];
    const float* oov  = (const float*)d_in[3];
    const float* Wq   = (const float*)d_in[4];
    const float* bq   = (const float*)d_in[5];
    const float* Wk   = (const float*)d_in[6];
    const float* bk   = (const float*)d_in[7];
    const float* Wv   = (const float*)d_in[8];
    const float* bv   = (const float*)d_in[9];
    const float* Wo   = (const float*)d_in[10];
    const float* bo   = (const float*)d_in[11];
    const float* lng  = (const float*)d_in[12];
    const float* lnb  = (const float*)d_in[13];
    const float* ls   = (const float*)d_in[14];
    float* out = (float*)d_out;

    pack_all_kernel<<<566, 256>>>(Wq, Wk, Wv, Wo);                                  // 1
    kv_kernel<<<dim3((T_LEN + ROWS_KV - 1) / ROWS_KV, 2), 256>>>(text, bk, bv, ls); // 2
    q_kernel<<<NROWS / ROWS_Q, 256>>>(tgt, qpos, bq);                               // 3
    attn_kernel<<<dim3(NHEAD, BATCH, 2), 128>>>(oov);                               // 4 <- profiled
    proj_kernel<<<NROWS / ROWS_P, 256>>>(tgt, bo, lng, lnb, out);                   // 5
}

// round 13
// speedup vs baseline: 2.2566x; 1.3795x over previous
#include <cuda_runtime.h>
#include <cuda_fp16.h>

#define D_MODEL 256
#define D_CLIP 768
#define NHEAD 8
#define HEAD_DIM 32
#define Q_LEN 100
#define BATCH 32
#define T_LEN 1203
#define T_PAD 1216
#define NROWS (Q_LEN * BATCH)   // 3200
#define LOG2E 1.4426950408889634f
#define TT 64
#define VT_PITCH 72             // 64 + 8 halfs: conflict-free V^T reads
#define OV_PITCH 72             // floats; <=2-way LDS conflicts

typedef unsigned long long u64;
typedef unsigned int u32;

// ---- scratch (device globals) ----
__device__ __half g_Khi[NHEAD * T_PAD * HEAD_DIM];   // K * scale*(1-a_h)*log2e, split hi
__device__ __half g_Klo[NHEAD * T_PAD * HEAD_DIM];
__device__ __half g_Vthi[NHEAD * HEAD_DIM * T_PAD];  // V transposed [h][d][t], split
__device__ __half g_Vtlo[NHEAD * HEAD_DIM * T_PAD];
__device__ __half g_Qhi[BATCH * NHEAD * Q_LEN * HEAD_DIM];
__device__ __half g_Qlo[BATCH * NHEAD * Q_LEN * HEAD_DIM];
__device__ float g_AT[BATCH * NHEAD * Q_LEN * HEAD_DIM];  // normalized attn out
__device__ float g_OOV[BATCH * Q_LEN * T_PAD];            // aligned-repacked oov
// packed transposed weights
__device__ float g_WqT4[D_MODEL * D_MODEL];
__device__ float g_WkT4[D_MODEL * D_CLIP];
__device__ float g_WvT4[D_MODEL * D_CLIP];
__device__ float g_WoT4[D_MODEL * D_MODEL];

// ---- packed fp32x2 helpers ----
__device__ __forceinline__ void unpk2(u64 v, float& lo, float& hi) {
    asm("mov.b64 {%0, %1}, %2;" : "=f"(lo), "=f"(hi) : "l"(v));
}
__device__ __forceinline__ u64 fma2(u64 a, u64 b, u64 c) {
    u64 d; asm("fma.rn.f32x2 %0, %1, %2, %3;" : "=l"(d) : "l"(a), "l"(b), "l"(c)); return d;
}
__device__ __forceinline__ float hsum2(u64 v) { float lo, hi; unpk2(v, lo, hi); return lo + hi; }
__device__ __forceinline__ float ex2(float x) {
    float r; asm("ex2.approx.f32 %0, %1;" : "=f"(r) : "f"(x)); return r;
}
// pack two f32 -> f16x2 (lo -> low half)
__device__ __forceinline__ u32 f2h2(float flo, float fhi) {
    u32 r; asm("cvt.rn.f16x2.f32 %0, %1, %2;" : "=r"(r) : "f"(fhi), "f"(flo)); return r;
}
__device__ __forceinline__ float2 h22f2(u32 h) {
    __half2 hh = *reinterpret_cast<__half2*>(&h);
    return __half22float2(hh);
}
__device__ __forceinline__ void mma16816(float* d, const u32* a, u32 b0, u32 b1) {
    asm volatile("mma.sync.aligned.m16n8k16.row.col.f32.f16.f16.f32 "
        "{%0,%1,%2,%3}, {%4,%5,%6,%7}, {%8,%9}, {%0,%1,%2,%3};"
        : "+f"(d[0]), "+f"(d[1]), "+f"(d[2]), "+f"(d[3])
        : "r"(a[0]), "r"(a[1]), "r"(a[2]), "r"(a[3]), "r"(b0), "r"(b1));
}
__device__ __forceinline__ void split16(float v, __half& hi, __half& lo) {
    hi = __float2half_rn(v);
    lo = __float2half_rn(v - __half2float(hi));
}

// ============================================================================
// Kernel 0a: pack weights + zero-fill K/V padding rows (t in [1203,1216)).
// ============================================================================
__global__ void pack_all_kernel(const float* __restrict__ Wq, const float* __restrict__ Wk,
                                const float* __restrict__ Wv, const float* __restrict__ Wo)
{
    const int idx = blockIdx.x * blockDim.x + threadIdx.x;
    if (idx < 131072) {
        const float* src; float* dst; int n4, id;
        if (idx < 16384)       { src = Wq; dst = g_WqT4; n4 = 64;  id = idx; }
        else if (idx < 65536)  { src = Wk; dst = g_WkT4; n4 = 192; id = idx - 16384; }
        else if (idx < 114688) { src = Wv; dst = g_WvT4; n4 = 192; id = idx - 65536; }
        else                   { src = Wo; dst = g_WoT4; n4 = 64;  id = idx - 114688; }
        int j = id / n4, c4 = id - j * n4;
        float4 v = ((const float4*)src)[(size_t)j * n4 + c4];
        ((float4*)dst)[(size_t)c4 * D_MODEL + j] = v;
    } else {
        int p = idx - 131072;                 // 13312 pad halfs (x2 arrays each)
        if (p < 6656) {
            int a = p / 3328, r = p % 3328;   // K pads: h, t in [1203,1216), d
            int h = r / 416, rr = r % 416;
            int t = T_LEN + rr / 32, d = rr % 32;
            __half* dst = a ? g_Klo : g_Khi;
            dst[((size_t)h * T_PAD + t) * 32 + d] = __half(0.0f);
        } else if (p < 13312) {
            int q = p - 6656;
            int a = q / 3328, r = q % 3328;   // Vt pads: row = h*32+d, t
            int row = r / 13, t = T_LEN + r % 13;
            __half* dst = a ? g_Vtlo : g_Vthi;
            dst[(size_t)row * T_PAD + t] = __half(0.0f);
        }
    }
}

// Kernel 0b: repack oov into 16B-aligned rows [b][q][T_PAD]
__global__ void oov_pack_kernel(const float* __restrict__ oov)
{
    const int total = BATCH * Q_LEN * T_LEN;
    for (int idx = blockIdx.x * blockDim.x + threadIdx.x; idx < total; idx += gridDim.x * blockDim.x) {
        int row = idx / T_LEN, t = idx - row * T_LEN;
        g_OOV[(size_t)row * T_PAD + t] = oov[idx];
    }
}

// ============================================================================
// Kernel 1: K or V projection (ROWS 16, dynamic smem). K: l2norm + fold
// scale*(1-a_h)*log2e, split fp16. V: split fp16, stored transposed [h][d][t].
// ============================================================================
#define ROWS_KV 16
__global__ __launch_bounds__(256, 2) void kv_kernel(
    const float* __restrict__ text, const float* __restrict__ bk,
    const float* __restrict__ bv, const float* __restrict__ lsp)
{
    extern __shared__ float s_text[];   // [ROWS_KV][768] = 48 KB
    const int tid = threadIdx.x;
    const int t0 = blockIdx.x * ROWS_KV;
    const int isV = blockIdx.y;
    const int nrows = min(ROWS_KV, T_LEN - t0);

    for (int idx = tid; idx < ROWS_KV * (D_CLIP / 4); idx += 256) {
        int r = idx / (D_CLIP / 4);
        float4 v = make_float4(0.f, 0.f, 0.f, 0.f);
        if (r < nrows) {
            int c4 = idx - r * (D_CLIP / 4);
            v = ((const float4*)(text + (size_t)(t0 + r) * D_CLIP))[c4];
        }
        ((float4*)s_text)[idx] = v;
    }
    __syncthreads();

    const int j = tid, head = j >> 5, lane = j & 31;
    u64 aA[ROWS_KV], aB[ROWS_KV];
#pragma unroll
    for (int r = 0; r < ROWS_KV; ++r) { aA[r] = aB[r] = 0ull; }

    const ulonglong2* wp = ((const ulonglong2*)(isV ? g_WvT4 : g_WkT4)) + j;
#pragma unroll 2
    for (int c4 = 0; c4 < D_CLIP / 4; ++c4) {
        ulonglong2 w4 = wp[(size_t)c4 * D_MODEL];
#pragma unroll
        for (int r = 0; r < ROWS_KV; ++r) {
            ulonglong2 x = *(const ulonglong2*)(s_text + r * D_CLIP + 4 * c4);
            aA[r] = fma2(x.x, w4.x, aA[r]);
            aB[r] = fma2(x.y, w4.y, aB[r]);
        }
    }

    if (isV) {
        const float bvj = bv[j];
        for (int r = 0; r < nrows; ++r) {
            int t = t0 + r;
            float v = hsum2(aA[r]) + hsum2(aB[r]) + bvj;
            __half hi, lo; split16(v, hi, lo);
            size_t o = (size_t)(head * 32 + lane) * T_PAD + t;
            g_Vthi[o] = hi; g_Vtlo[o] = lo;
        }
    } else {
        const float scale = fminf(expf(lsp[0]), 100.0f);
        const float kfac = scale * (1.0f - (float)head * (1.0f / 7.0f)) * LOG2E;
        const float bkj = bk[j];
        for (int r = 0; r < nrows; ++r) {
            float kk = hsum2(aA[r]) + hsum2(aB[r]) + bkj;
            float ss = kk * kk;
#pragma unroll
            for (int off = 16; off > 0; off >>= 1) ss += __shfl_xor_sync(0xffffffffu, ss, off);
            float val = kk / fmaxf(sqrtf(ss), 1e-6f) * kfac;
            __half hi, lo; split16(val, hi, lo);
            size_t o = ((size_t)head * T_PAD + t0 + r) * 32 + lane;
            g_Khi[o] = hi; g_Klo[o] = lo;
        }
    }
}

// ============================================================================
// Kernel 2: Q projection + l2norm, split fp16, [b][h][q][d]  (ROWS 16)
// ============================================================================
#define ROWS_Q 16
__global__ __launch_bounds__(256, 2) void q_kernel(
    const float* __restrict__ tgt, const float* __restrict__ qpos,
    const float* __restrict__ bq)
{
    __shared__ float s_in[ROWS_Q][D_MODEL];   // 16 KB
    const int tid = threadIdx.x;
    const int r0 = blockIdx.x * ROWS_Q;

    for (int idx = tid; idx < ROWS_Q * (D_MODEL / 4); idx += 256) {
        int r = idx >> 6, c4 = idx & 63;
        const float4 a = ((const float4*)(tgt  + (size_t)(r0 + r) * D_MODEL))[c4];
        const float4 p = ((const float4*)(qpos + (size_t)(r0 + r) * D_MODEL))[c4];
        ((float4*)(&s_in[r][0]))[c4] = make_float4(a.x + p.x, a.y + p.y, a.z + p.z, a.w + p.w);
    }
    __syncthreads();

    const int j = tid, head = j >> 5, lane = j & 31;
    u64 aA[ROWS_Q], aB[ROWS_Q];
#pragma unroll
    for (int r = 0; r < ROWS_Q; ++r) { aA[r] = aB[r] = 0ull; }

    const ulonglong2* wqp = ((const ulonglong2*)g_WqT4) + j;
#pragma unroll 2
    for (int c4 = 0; c4 < D_MODEL / 4; ++c4) {
        ulonglong2 w4 = wqp[(size_t)c4 * D_MODEL];
#pragma unroll
        for (int r = 0; r < ROWS_Q; ++r) {
            ulonglong2 x = *(const ulonglong2*)(&s_in[r][4 * c4]);
            aA[r] = fma2(x.x, w4.x, aA[r]);
            aB[r] = fma2(x.y, w4.y, aB[r]);
        }
    }

    const float bqj = bq[j];
    for (int r = 0; r < ROWS_Q; ++r) {
        float qq = hsum2(aA[r]) + hsum2(aB[r]) + bqj;
        float ss = qq * qq;
#pragma unroll
        for (int off = 16; off > 0; off >>= 1) ss += __shfl_xor_sync(0xffffffffu, ss, off);
        float val = qq / fmaxf(sqrtf(ss), 1e-6f);
        int row = r0 + r;
        int qi = row >> 5, b = row & 31;
        __half hi, lo; split16(val, hi, lo);
        size_t o = ((size_t)((b * NHEAD) + head) * Q_LEN + qi) * HEAD_DIM + lane;
        g_Qhi[o] = hi; g_Qlo[o] = lo;
    }
}

// ============================================================================
// Kernel 3: HMMA flash attention. Block = (h, b, qhalf); 4 warps x m16 queries.
// Split-fp16 (hi+lo) 3-MMA GEMMs; oov staged through smem (coalesced float4).
// ============================================================================
__global__ __launch_bounds__(128, 4) void attn_kernel()
{
    const int h = blockIdx.x, b = blockIdx.y, qc = blockIdx.z;
    const int tid = threadIdx.x;
    const int warp = tid >> 5, lane = tid & 31;
    const int g = lane >> 2, c = lane & 3;
    const int q0 = qc * 64 + warp * 16;
    const int r0 = min(q0 + g, Q_LEN - 1);
    const int r1 = min(q0 + g + 8, Q_LEN - 1);

    __shared__ __align__(16) __half sKhi[64 * 32], sKlo[64 * 32];
    __shared__ __align__(16) __half sVhi[32 * VT_PITCH], sVlo[32 * VT_PITCH];
    __shared__ __align__(16) float sOV[64 * OV_PITCH];   // 18.4 KB

    // ---- Q a-frags (2 ksteps x 4 regs, hi+lo) ----
    u32 qa_hi[2][4], qa_lo[2][4];
    {
        const __half* Qh = g_Qhi + (size_t)(b * NHEAD + h) * Q_LEN * HEAD_DIM;
        const __half* Ql = g_Qlo + (size_t)(b * NHEAD + h) * Q_LEN * HEAD_DIM;
#pragma unroll
        for (int ks = 0; ks < 2; ++ks) {
            int col = 16 * ks + 2 * c;
            qa_hi[ks][0] = *(const u32*)&Qh[r0 * 32 + col];
            qa_hi[ks][1] = *(const u32*)&Qh[r1 * 32 + col];
            qa_hi[ks][2] = *(const u32*)&Qh[r0 * 32 + col + 8];
            qa_hi[ks][3] = *(const u32*)&Qh[r1 * 32 + col + 8];
            qa_lo[ks][0] = *(const u32*)&Ql[r0 * 32 + col];
            qa_lo[ks][1] = *(const u32*)&Ql[r1 * 32 + col];
            qa_lo[ks][2] = *(const u32*)&Ql[r0 * 32 + col + 8];
            qa_lo[ks][3] = *(const u32*)&Ql[r1 * 32 + col + 8];
        }
    }

    float O[4][4];
#pragma unroll
    for (int dt = 0; dt < 4; ++dt)
#pragma unroll
        for (int e = 0; e < 4; ++e) O[dt][e] = 0.f;
    float m0 = -1e30f, m1 = -1e30f, l0 = 0.f, l1 = 0.f;

    const float ap = (float)h * (1.0f / 7.0f) * LOG2E;
    const bool use_qk = (h != NHEAD - 1);
    const bool use_ov = (h != 0);

    const int kbase = g * 32 + 2 * c;
    const int vbase = g * VT_PITCH + 2 * c;
    const float* so0 = sOV + (warp * 16 + g) * OV_PITCH + 2 * c;
    const float* so1 = so0 + 8 * OV_PITCH;

    for (int t0 = 0; t0 < T_LEN; t0 += TT) {
        __syncthreads();
        // ---- stage chunk: K (hi/lo), V^T (hi/lo), oov tile ----
        {
            const float4* srcKh = (const float4*)(g_Khi + ((size_t)h * T_PAD + t0) * 32);
            const float4* srcKl = (const float4*)(g_Klo + ((size_t)h * T_PAD + t0) * 32);
            ((float4*)sKhi)[tid] = srcKh[tid];
            ((float4*)sKhi)[tid + 128] = srcKh[tid + 128];
            ((float4*)sKlo)[tid] = srcKl[tid];
            ((float4*)sKlo)[tid + 128] = srcKl[tid + 128];
            const float4* srcVh = (const float4*)g_Vthi;
            const float4* srcVl = (const float4*)g_Vtlo;
            int u1 = tid, u2 = tid + 128;
            int d1 = u1 >> 3, s1 = u1 & 7, d2 = u2 >> 3, s2 = u2 & 7;
            ((float4*)sVhi)[d1 * 9 + s1] = srcVh[(size_t)(h * 32 + d1) * (T_PAD / 8) + (t0 >> 3) + s1];
            ((float4*)sVhi)[d2 * 9 + s2] = srcVh[(size_t)(h * 32 + d2) * (T_PAD / 8) + (t0 >> 3) + s2];
            ((float4*)sVlo)[d1 * 9 + s1] = srcVl[(size_t)(h * 32 + d1) * (T_PAD / 8) + (t0 >> 3) + s1];
            ((float4*)sVlo)[d2 * 9 + s2] = srcVl[(size_t)(h * 32 + d2) * (T_PAD / 8) + (t0 >> 3) + s2];
            if (use_ov) {
                // 64 rows x 16 float4; row = block-local query (clamped), cols t0..t0+63
#pragma unroll
                for (int it = 0; it < 8; ++it) {
                    int idx = tid + it * 128;
                    int r = idx >> 4, c4 = idx & 15;
                    int qrow = min(qc * 64 + r, Q_LEN - 1);
                    float4 v = ((const float4*)(g_OOV + (size_t)(b * Q_LEN + qrow) * T_PAD + t0))[c4];
                    ((float4*)(sOV + r * OV_PITCH))[c4] = v;
                }
            }
        }
        __syncthreads();

        // ---- S = Q K^T (8 n-tiles of 8 keys) ----
        float s[8][4];
#pragma unroll
        for (int j = 0; j < 8; ++j)
#pragma unroll
            for (int e = 0; e < 4; ++e) s[j][e] = 0.f;

        if (use_qk) {
#pragma unroll
            for (int j = 0; j < 8; ++j) {
#pragma unroll
                for (int ks = 0; ks < 2; ++ks) {
                    const __half* kh = sKhi + j * 256 + kbase + 16 * ks;
                    const __half* kl = sKlo + j * 256 + kbase + 16 * ks;
                    u32 bh0 = *(const u32*)kh;
                    u32 bh1 = *(const u32*)(kh + 8);
                    u32 bl0 = *(const u32*)kl;
                    u32 bl1 = *(const u32*)(kl + 8);
                    mma16816(s[j], qa_hi[ks], bh0, bh1);
                    mma16816(s[j], qa_hi[ks], bl0, bl1);
                    mma16816(s[j], qa_lo[ks], bh0, bh1);
                }
            }
        }
        if (use_ov) {
#pragma unroll
            for (int j = 0; j < 8; ++j) {
                float2 o0 = *(const float2*)(so0 + 8 * j);
                float2 o1 = *(const float2*)(so1 + 8 * j);
                s[j][0] = fmaf(ap, o0.x, s[j][0]);
                s[j][1] = fmaf(ap, o0.y, s[j][1]);
                s[j][2] = fmaf(ap, o1.x, s[j][2]);
                s[j][3] = fmaf(ap, o1.y, s[j][3]);
            }
        }
        if (t0 + TT > T_LEN) {
#pragma unroll
            for (int j = 0; j < 8; ++j) {
                int t = t0 + 8 * j + 2 * c;
                if (t >= T_LEN)     { s[j][0] = -1e30f; s[j][2] = -1e30f; }
                if (t + 1 >= T_LEN) { s[j][1] = -1e30f; s[j][3] = -1e30f; }
            }
        }

        // ---- online softmax (log2 domain) ----
        float cm0 = s[0][0], cm1 = s[0][2];
#pragma unroll
        for (int j = 0; j < 8; ++j) {
            cm0 = fmaxf(cm0, fmaxf(s[j][0], s[j][1]));
            cm1 = fmaxf(cm1, fmaxf(s[j][2], s[j][3]));
        }
        cm0 = fmaxf(cm0, __shfl_xor_sync(0xffffffffu, cm0, 1));
        cm0 = fmaxf(cm0, __shfl_xor_sync(0xffffffffu, cm0, 2));
        cm1 = fmaxf(cm1, __shfl_xor_sync(0xffffffffu, cm1, 1));
        cm1 = fmaxf(cm1, __shfl_xor_sync(0xffffffffu, cm1, 2));
        float nm0 = fmaxf(m0, cm0), nm1 = fmaxf(m1, cm1);
        float rs0 = ex2(m0 - nm0), rs1 = ex2(m1 - nm1);
        m0 = nm0; m1 = nm1;
        l0 *= rs0; l1 *= rs1;
#pragma unroll
        for (int dt = 0; dt < 4; ++dt) {
            O[dt][0] *= rs0; O[dt][1] *= rs0;
            O[dt][2] *= rs1; O[dt][3] *= rs1;
        }
#pragma unroll
        for (int j = 0; j < 8; ++j) {
            s[j][0] = ex2(s[j][0] - m0);
            s[j][1] = ex2(s[j][1] - m0);
            s[j][2] = ex2(s[j][2] - m1);
            s[j][3] = ex2(s[j][3] - m1);
            l0 += s[j][0] + s[j][1];
            l1 += s[j][2] + s[j][3];
        }

        // ---- O += P V, per kstep: build P a-frags (hi/lo), then 4 d-tiles ----
#pragma unroll
        for (int ks = 0; ks < 4; ++ks) {
            const int j0 = 2 * ks, j1 = 2 * ks + 1;
            u32 pa_hi[4], pa_lo[4];
            pa_hi[0] = f2h2(s[j0][0], s[j0][1]);
            pa_hi[1] = f2h2(s[j0][2], s[j0][3]);
            pa_hi[2] = f2h2(s[j1][0], s[j1][1]);
            pa_hi[3] = f2h2(s[j1][2], s[j1][3]);
#pragma unroll
            for (int e = 0; e < 4; ++e) {
                const int jj = (e < 2) ? j0 : j1;
                const int base = (e & 1) ? 2 : 0;
                float2 hf = h22f2(pa_hi[e]);
                pa_lo[e] = f2h2(s[jj][base] - hf.x, s[jj][base + 1] - hf.y);
            }
#pragma unroll
            for (int dt = 0; dt < 4; ++dt) {
                const __half* vh = sVhi + dt * 8 * VT_PITCH + vbase + 16 * ks;
                const __half* vl = sVlo + dt * 8 * VT_PITCH + vbase + 16 * ks;
                u32 bh0 = *(const u32*)vh;
                u32 bh1 = *(const u32*)(vh + 8);
                u32 bl0 = *(const u32*)vl;
                u32 bl1 = *(const u32*)(vl + 8);
                mma16816(O[dt], pa_hi, bh0, bh1);
                mma16816(O[dt], pa_hi, bl0, bl1);
                mma16816(O[dt], pa_lo, bh0, bh1);
            }
        }
    }

    // ---- epilogue: reduce l across quad, normalize, store ----
    l0 += __shfl_xor_sync(0xffffffffu, l0, 1);
    l0 += __shfl_xor_sync(0xffffffffu, l0, 2);
    l1 += __shfl_xor_sync(0xffffffffu, l1, 1);
    l1 += __shfl_xor_sync(0xffffffffu, l1, 2);
    const float inv0 = 1.0f / l0, inv1 = 1.0f / l1;
    float* dstBase = g_AT + (size_t)(b * NHEAD + h) * Q_LEN * HEAD_DIM;
    if (q0 + g < Q_LEN) {
        float* d0 = dstBase + (size_t)(q0 + g) * HEAD_DIM + 2 * c;
#pragma unroll
        for (int dt = 0; dt < 4; ++dt)
            *(float2*)(d0 + 8 * dt) = make_float2(O[dt][0] * inv0, O[dt][1] * inv0);
    }
    if (q0 + g + 8 < Q_LEN) {
        float* d1 = dstBase + (size_t)(q0 + g + 8) * HEAD_DIM + 2 * c;
#pragma unroll
        for (int dt = 0; dt < 4; ++dt)
            *(float2*)(d1 + 8 * dt) = make_float2(O[dt][2] * inv1, O[dt][3] * inv1);
    }
}

// ============================================================================
// Kernel 4: output projection + residual + LayerNorm (ROWS 16)
// ============================================================================
#define ROWS_P 16
__global__ __launch_bounds__(256, 2) void proj_kernel(
    const float* __restrict__ tgt, const float* __restrict__ bo,
    const float* __restrict__ ln_g, const float* __restrict__ ln_b, float* __restrict__ out)
{
    __shared__ float s_att[ROWS_P][D_MODEL];
    __shared__ float s_y[ROWS_P][D_MODEL];
    __shared__ float s_mu[ROWS_P], s_rs[ROWS_P];
    const int tid = threadIdx.x;
    const int r0 = blockIdx.x * ROWS_P;
    const int j = tid, head = j >> 5, lane = j & 31;

    for (int r = 0; r < ROWS_P; ++r) {
        int row = r0 + r, qi = row >> 5, b = row & 31;
        s_att[r][j] = g_AT[((size_t)((b * NHEAD) + head) * Q_LEN + qi) * HEAD_DIM + lane];
    }
    __syncthreads();

    u64 accA[ROWS_P], accB[ROWS_P];
#pragma unroll
    for (int r = 0; r < ROWS_P; ++r) { accA[r] = accB[r] = 0ull; }
    const ulonglong2* wop = ((const ulonglong2*)g_WoT4) + j;
#pragma unroll 2
    for (int c4 = 0; c4 < D_MODEL / 4; ++c4) {
        ulonglong2 w4 = wop[(size_t)c4 * D_MODEL];
#pragma unroll
        for (int r = 0; r < ROWS_P; ++r) {
            ulonglong2 x = *(const ulonglong2*)(&s_att[r][4 * c4]);
            accA[r] = fma2(x.x, w4.x, accA[r]);
            accB[r] = fma2(x.y, w4.y, accB[r]);
        }
    }

    const float boj = bo[j];
    for (int r = 0; r < ROWS_P; ++r) {
        int row = r0 + r;
        s_y[r][j] = hsum2(accA[r]) + hsum2(accB[r]) + boj + tgt[(size_t)row * D_MODEL + j];
    }
    __syncthreads();

    {
        const int w = tid >> 5, ln = tid & 31;
#pragma unroll
        for (int rr = 0; rr < 2; ++rr) {
            int r = 2 * w + rr;
            float sval = 0.f, sq = 0.f;
            for (int cc = ln; cc < D_MODEL; cc += 32) { float v = s_y[r][cc]; sval += v; sq += v * v; }
#pragma unroll
            for (int off = 16; off > 0; off >>= 1) {
                sval += __shfl_xor_sync(0xffffffffu, sval, off);
                sq   += __shfl_xor_sync(0xffffffffu, sq, off);
            }
            if (ln == 0) {
                float mu = sval * (1.0f / D_MODEL);
                s_mu[r] = mu;
                s_rs[r] = rsqrtf(sq * (1.0f / D_MODEL) - mu * mu + 1e-5f);
            }
        }
    }
    __syncthreads();

    const float gg = ln_g[j], bb = ln_b[j];
    for (int r = 0; r < ROWS_P; ++r) {
        int row = r0 + r;
        out[(size_t)row * D_MODEL + j] = (s_y[r][j] - s_mu[r]) * s_rs[r] * gg + bb;
    }
}

// ============================================================================
extern "C" void kernel_launch(void* const* d_in, const int* in_sizes, int n_in,
                              void* d_out, int out_size)
{
    const float* tgt  = (const float*)d_in[0];
    const float* text = (const float*)d_in[1];
    const float* qpos = (const float*)d_in[2];
    const float* oov  = (const float*)d_in[3];
    const float* Wq   = (const float*)d_in[4];
    const float* bq   = (const float*)d_in[5];
    const float* Wk   = (const float*)d_in[6];
    const float* bk   = (const float*)d_in[7];
    const float* Wv   = (const float*)d_in[8];
    const float* bv   = (const float*)d_in[9];
    const float* Wo   = (const float*)d_in[10];
    const float* bo   = (const float*)d_in[11];
    const float* lng  = (const float*)d_in[12];
    const float* lnb  = (const float*)d_in[13];
    const float* ls   = (const float*)d_in[14];
    float* out = (float*)d_out;

    pack_all_kernel<<<566, 256>>>(Wq, Wk, Wv, Wo);
    oov_pack_kernel<<<2048, 256>>>(oov);

    const int kv_smem = ROWS_KV * D_CLIP * (int)sizeof(float);   // 48 KB
    cudaFuncSetAttribute(kv_kernel, cudaFuncAttributeMaxDynamicSharedMemorySize, kv_smem);
    kv_kernel<<<dim3((T_LEN + ROWS_KV - 1) / ROWS_KV, 2), 256, kv_smem>>>(text, bk, bv, ls);

    q_kernel<<<NROWS / ROWS_Q, 256>>>(tgt, qpos, bq);
    attn_kernel<<<dim3(NHEAD, BATCH, 2), 128>>>();
    proj_kernel<<<NROWS / ROWS_P, 256>>>(tgt, bo, lng, lnb, out);
}